// round 12
// baseline (speedup 1.0000x reference)
#include <cuda_runtime.h>
#include <cuda_fp16.h>
#include <math.h>

#define KNOTS 64
#define WCOLS 7168          // 7 paths * 32 u * 32 w
#define MAXN  4096
#define MAXE  32768
#define NCELLS 63           // cell_of in [0,62]
#define PERM_SZ (MAXE + 32 * 64)   // per-cell pad to mult of 32
#define NTILES  (PERM_SZ / 32)     // 1088 CTAs, 2 sub-tiles each
#define NASTRIDE 162        // even stride -> 8B-aligned red.v2 targets

// B layouts (halfs), rows padded for conflict-free ldmatrix
#define ST_SG 136           // K=128 + 8 pad
#define ST_V  200           // K=192 + 8 pad
#define BSG_CELL (64 * ST_SG)   // 8704 halfs
#define BV_CELL  (32 * ST_V)    // 6400 halfs

// ---------------- scratch (device globals; no allocation allowed) ----------------
__device__ __align__(16) __half g_Bsg[64 * BSG_CELL];   // [cell][n=64][k=128 pad 136]
__device__ __align__(16) __half g_Bv [64 * BV_CELL];    // [cell][n=32][k=192 pad 200]
__device__ float g_nodeacc[MAXN * NASTRIDE];
__device__ int   g_binCount[64];
__device__ int   g_binCursor[64];
__device__ int   g_perm[PERM_SZ];
__device__ int   g_tileCell[NTILES];

__device__ __forceinline__ int cell_of(float L) {
    float t = L * ((float)(KNOTS - 1) / 5.0f);
    int i = (int)floorf(t);
    if (i < 0) i = 0;
    if (i > KNOTS - 2) i = KNOTS - 2;
    return i;
}

__device__ __forceinline__ unsigned smaddr(const void* p) {
    return (unsigned)__cvta_generic_to_shared(p);
}
__device__ __forceinline__ void ldsm4(unsigned& a0, unsigned& a1, unsigned& a2, unsigned& a3,
                                      unsigned addr) {
    asm volatile("ldmatrix.sync.aligned.m8n8.x4.shared.b16 {%0,%1,%2,%3}, [%4];"
                 : "=r"(a0), "=r"(a1), "=r"(a2), "=r"(a3) : "r"(addr));
}
__device__ __forceinline__ void ldsm2(unsigned& b0, unsigned& b1, unsigned addr) {
    asm volatile("ldmatrix.sync.aligned.m8n8.x2.shared.b16 {%0,%1}, [%2];"
                 : "=r"(b0), "=r"(b1) : "r"(addr));
}
__device__ __forceinline__ void mma16816(float* c, unsigned a0, unsigned a1, unsigned a2,
                                         unsigned a3, unsigned b0, unsigned b1) {
    asm volatile(
        "mma.sync.aligned.m16n8k16.row.col.f32.f16.f16.f32 "
        "{%0,%1,%2,%3}, {%4,%5,%6,%7}, {%8,%9}, {%0,%1,%2,%3};\n"
        : "+f"(c[0]), "+f"(c[1]), "+f"(c[2]), "+f"(c[3])
        : "r"(a0), "r"(a1), "r"(a2), "r"(a3), "r"(b0), "r"(b1));
}
__device__ __forceinline__ void red2(float* p, float a, float b) {
    asm volatile("red.global.add.v2.f32 [%0], {%1, %2};" :: "l"(p), "f"(a), "f"(b) : "memory");
}

// ---------------- kernel 1: build per-cell B matrices + histogram ----------------
// Grid (4, 28), block 256: 16 knot-rows x 256 cols each.
__global__ void k_build(const float* __restrict__ Wfc1, const float* __restrict__ Wfc2,
                        const float* __restrict__ len, int E) {
    __shared__ float sm_h[64][17];
    __shared__ int   sm_hist[64];
    const int t = threadIdx.x;
    const int kbase = blockIdx.x * 16;
    const int col = blockIdx.y * 256 + t;

    if (t < 64) sm_hist[t] = 0;
    __syncthreads();

    {
        int gid = (blockIdx.y * gridDim.x + blockIdx.x) * 256 + t;
        int stride = gridDim.x * gridDim.y * 256;
        for (int e = gid; e < E; e += stride)
            atomicAdd(&sm_hist[cell_of(len[e])], 1);
    }

    for (int idx = t; idx < 16 * 64; idx += 256) {
        int kk = idx >> 6, c = idx & 63;
        float r = (float)(kbase + kk) * (5.0f / (float)(KNOTS - 1));
        float pre = 0.0f;
        #pragma unroll
        for (int j = 0; j < 8; j++) {
            float d = r - (float)j * (5.0f / 7.0f);
            float rad = expf(-d * d * 0.98f);
            pre += rad * Wfc1[j * 64 + c];
        }
        pre *= 0.35355339059327373f;                 // 1/sqrt(8)
        sm_h[c][kk] = pre / (1.0f + expf(-pre));     // silu
    }
    __syncthreads();

    if (t < 64 && sm_hist[t] > 0) atomicAdd(&g_binCount[t], sm_hist[t]);

    float acc[16];
    #pragma unroll
    for (int kk = 0; kk < 16; kk++) acc[kk] = 0.0f;
    #pragma unroll 4
    for (int c = 0; c < 64; c++) {
        float wv = __ldg(&Wfc2[c * WCOLS + col]);
        #pragma unroll
        for (int kk = 0; kk < 16; kk++) acc[kk] = fmaf(sm_h[c][kk], wv, acc[kk]);
    }
    float sc = (col < 4096) ? 0.015625f : 0.022097086912079608f;

    const int p = col >> 10, u = (col >> 5) & 31, w = col & 31;
    #pragma unroll
    for (int kk = 0; kk < 16; kk++) {
        __half hv = __float2half_rn(acc[kk] * sc);
        int row = kbase + kk;
        if (p < 4) {
            int n = (p >> 1) * 32 + w;         // S cols 0-31, G cols 32-63
            int kb = (p & 1) * 32 + u;         // feat*32 + u
            if (row <= 62) g_Bsg[(size_t)row * BSG_CELL + n * ST_SG + kb] = hv;        // knot0
            if (row >= 1)  g_Bsg[(size_t)(row - 1) * BSG_CELL + n * ST_SG + 64 + kb] = hv;  // knot1
        } else {
            int kb = (p - 4) * 32 + u;
            if (row <= 62) g_Bv[(size_t)row * BV_CELL + w * ST_V + kb] = hv;
            if (row >= 1)  g_Bv[(size_t)(row - 1) * BV_CELL + w * ST_V + 96 + kb] = hv;
        }
    }
}

// ---------------- kernel 2: scan (pad-32) + tile map + bin reset ----------------
__global__ void k_scan() {
    int t = threadIdx.x;   // 32
    int c0 = 2 * t, c1 = 2 * t + 1;
    int n0 = (c0 < NCELLS) ? g_binCount[c0] : 0;
    int n1 = (c1 < NCELLS) ? g_binCount[c1] : 0;
    int p0 = (n0 + 31) & ~31, p1 = (n1 + 31) & ~31;
    int s = p0 + p1;
    int x = s;
    #pragma unroll
    for (int o = 1; o < 32; o <<= 1) {
        int y = __shfl_up_sync(0xffffffffu, x, o);
        if (t >= o) x += y;
    }
    int base0 = x - s;
    int base1 = base0 + p0;
    g_binCursor[c0] = base0;
    g_binCursor[c1] = base1;
    for (int i = n0; i < p0; i++) g_perm[base0 + i] = -1;
    for (int i = n1; i < p1; i++) g_perm[base1 + i] = -1;
    for (int i = 0; i < (p0 >> 5); i++) g_tileCell[(base0 >> 5) + i] = c0;
    for (int i = 0; i < (p1 >> 5); i++) g_tileCell[(base1 >> 5) + i] = c1;
    int tot = __shfl_sync(0xffffffffu, x, 31);
    for (int i = (tot >> 5) + t; i < NTILES; i += 32) g_tileCell[i] = -1;
    g_binCount[c0] = 0;
    g_binCount[c1] = 0;
}

// ---------------- kernel 3: two-level scatter + nodeacc zeroing ----------------
__global__ void k_scatterzero(const float* __restrict__ len, int E, int accTotal) {
    __shared__ int sCnt[64];
    __shared__ int sBase[64];
    const int t = threadIdx.x;
    const int gid = blockIdx.x * 256 + t;

    if (t < 64) sCnt[t] = 0;

    for (int i = gid; i < accTotal; i += gridDim.x * 256) g_nodeacc[i] = 0.0f;
    __syncthreads();

    int e = -1, bin = 0, rank = 0;
    if (gid < E) {
        e = gid;
        bin = cell_of(len[e]);
        rank = atomicAdd(&sCnt[bin], 1);
    }
    __syncthreads();
    if (t < 64) sBase[t] = (sCnt[t] > 0) ? atomicAdd(&g_binCursor[t], sCnt[t]) : 0;
    __syncthreads();
    if (e >= 0) g_perm[sBase[bin] + rank] = e;
}

// ---------------- kernel 4 (profiled slot): tensor-core edge kernel ----------------
// CTA = 32 same-cell edges = 2 sequential 16-edge sub-tiles sharing one B stage.
// B-staging stores issue before rep-0 feature phase; first sync covers both.
#define OFF_AV  2176
#define OFF_BSG 11776
#define OFF_BV  20480
#define SMEM_HALFS 26880
#define SMEM_BYTES (SMEM_HALFS * 2 + 128)

__global__ __launch_bounds__(256, 3) void k_edge_mma(
        const float* __restrict__ x, const float* __restrict__ attr,
        const float* __restrict__ len, const int* __restrict__ src,
        const int* __restrict__ dst) {
    extern __shared__ __align__(16) __half smh[];
    __half* sAsg = smh;
    __half* sAv  = smh + OFF_AV;
    __half* sBsg = smh + OFF_BSG;
    __half* sBv  = smh + OFF_BV;
    int* sEdge = (int*)(smh + SMEM_HALFS);
    int* sDst  = sEdge + 16;

    const int tile = blockIdx.x;
    const int cell = g_tileCell[tile];
    if (cell < 0) return;
    const int t = threadIdx.x;
    const int lane = t & 31, warp = t >> 5;

    // ---- stage B (coalesced); no sync yet — overlapped with rep-0 features ----
    {
        const uint4* gb = (const uint4*)(g_Bsg + (size_t)cell * BSG_CELL);
        uint4* sb = (uint4*)sBsg;
        for (int i = t; i < BSG_CELL / 8; i += 256) sb[i] = gb[i];
        const uint4* gv = (const uint4*)(g_Bv + (size_t)cell * BV_CELL);
        uint4* sv = (uint4*)sBv;
        for (int i = t; i < BV_CELL / 8; i += 256) sv[i] = gv[i];
    }

    const int l15 = lane & 15;
    const int aoff = (lane >> 4) * 8;          // A fragment col-half select
    const int boff = ((l15 >> 3) & 1) * 8;     // B fragment col-half select
    const int bn   = l15 & 7;                  // B fragment row-in-tile
    const float IS3 = 0.5773502691896258f;
    const float cA = 0.31622776601683794f;
    const float cB = 0.18257418583505536f;
    const float cC = 0.36514837167011072f;

    #pragma unroll
    for (int rep = 0; rep < 2; rep++) {
        // ---- feature phase: thread t -> edge e = t>>4, u in {t&15, (t&15)+16} ----
        {
            const int e = t >> 4, u0 = t & 15;
            int eg = g_perm[tile * 32 + rep * 16 + e];
            float f = 0.0f;
            float y0 = 0, y10 = 0, y11 = 0, y12 = 0;
            float M00 = 0, M01 = 0, M02 = 0, M10 = 0, M11 = 0, M12 = 0, M20 = 0, M21 = 0, M22 = 0;
            const float* xr = x;   // dummy
            if (eg >= 0) {
                float L = len[eg];
                float tp = L * ((float)(KNOTS - 1) / 5.0f) - (float)cell;
                f = fminf(fmaxf(tp, 0.0f), 1.0f);
                const float* ar = attr + eg * 9;
                y0 = ar[0]; y10 = ar[1]; y11 = ar[2]; y12 = ar[3];
                float y20 = ar[4], y21 = ar[5], y22 = ar[6], y23 = ar[7], y24 = ar[8];
                M00 = -cB * y22 + cA * y24;
                M01 =  cA * y20;  M02 = cA * y23;
                M10 =  cA * y20;  M11 = -cB * y22 - cA * y24;  M12 = cA * y21;
                M20 =  cA * y23;  M21 = cA * y21;              M22 = cC * y22;
                xr = x + (size_t)src[eg] * 128;
            }
            float g1 = 1.0f - f;
            if (u0 == 0) {
                sEdge[e] = eg;
                int dn = (eg >= 0) ? dst[eg] : 0;
                sDst[e] = dn;
                if (eg >= 0) atomicAdd(g_nodeacc + (size_t)dn * NASTRIDE + 160, 1.0f);
            }
            #pragma unroll
            for (int half_ = 0; half_ < 2; half_++) {
                int u = u0 + half_ * 16;
                float F[11];
                #pragma unroll
                for (int k = 0; k < 11; k++) F[k] = 0.0f;
                if (eg >= 0) {
                    float sj = xr[u];
                    float v0 = xr[32 + 3 * u], v1 = xr[33 + 3 * u], v2 = xr[34 + 3 * u];
                    F[0] = sj * y0;
                    F[1] = (v0 * y10 + v1 * y11 + v2 * y12) * IS3;
                    float sy = sj * IS3;
                    F[2] = sy * y10; F[3] = sy * y11; F[4] = sy * y12;
                    float yv = y0 * IS3;
                    F[5] = v0 * yv; F[6] = v1 * yv; F[7] = v2 * yv;
                    F[8]  = v0 * M00 + v1 * M10 + v2 * M20;
                    F[9]  = v0 * M01 + v1 * M11 + v2 * M21;
                    F[10] = v0 * M02 + v1 * M12 + v2 * M22;
                }
                __half* asg = sAsg + e * ST_SG;
                asg[u]      = __float2half_rn(F[0] * g1);
                asg[32 + u] = __float2half_rn(F[1] * g1);
                asg[64 + u] = __float2half_rn(F[0] * f);
                asg[96 + u] = __float2half_rn(F[1] * f);
                #pragma unroll
                for (int kc = 0; kc < 3; kc++) {
                    __half* av = sAv + (kc * 16 + e) * ST_V;
                    av[u]        = __float2half_rn(F[2 + kc] * g1);   // t01 -> path4
                    av[32 + u]   = __float2half_rn(F[5 + kc] * g1);   // t10 -> path5
                    av[64 + u]   = __float2half_rn(F[8 + kc] * g1);   // t12 -> path6
                    av[96 + u]   = __float2half_rn(F[2 + kc] * f);
                    av[128 + u]  = __float2half_rn(F[5 + kc] * f);
                    av[160 + u]  = __float2half_rn(F[8 + kc] * f);
                }
            }
        }
        __syncthreads();   // rep0: covers B staging + A; rep1: A only

        // ---- MMA phase: 20 work items (8 SG n-tiles, 12 V (kcomp,n)-tiles) ----
        for (int item = warp; item < 20; item += 8) {
            float c[4] = {0.f, 0.f, 0.f, 0.f};
            const __half *A, *B;
            int K, stA, nb;
            int isV = (item >= 8);
            int kcomp = 0;
            if (!isV) {
                A = sAsg; B = sBsg; K = 8; stA = ST_SG; nb = item * 8;
            } else {
                int idx = item - 8;
                kcomp = idx >> 2;
                int nt = idx & 3;
                A = sAv + kcomp * 16 * ST_V; B = sBv; K = 12; stA = ST_V; nb = nt * 8;
            }
            const int stB = stA;
            const unsigned aBase = smaddr(A + l15 * stA + aoff);
            const unsigned bBase = smaddr(B + (nb + bn) * stB + boff);
            for (int ks = 0; ks < K; ks++) {
                int kb2 = ks * 32;   // ks*16 halfs = ks*32 bytes
                unsigned a0, a1, a2, a3, b0, b1;
                ldsm4(a0, a1, a2, a3, aBase + kb2);
                ldsm2(b0, b1, bBase + kb2);
                mma16816(c, a0, a1, a2, a3, b0, b1);
            }
            // epilogue: rows r0, r0+8 = edges; cols cp, cp+1 contiguous -> red2
            const int r0 = lane >> 2, cp = (lane & 3) * 2;
            int ed0 = sEdge[r0], ed1 = sEdge[r0 + 8];
            int col = (!isV) ? (item * 8 + cp) : (64 + kcomp * 32 + nb + cp);
            if (ed0 >= 0) red2(g_nodeacc + (size_t)sDst[r0] * NASTRIDE + col, c[0], c[1]);
            if (ed1 >= 0) red2(g_nodeacc + (size_t)sDst[r0 + 8] * NASTRIDE + col, c[2], c[3]);
        }
        if (rep == 0) __syncthreads();   // A reads done before rep-1 overwrites
    }
}

// ---------------- kernel 5: mean, gating, self-connection, norms ----------------
// nodeacc layout: [0:32) S, [32:64) G, [64+kcomp*32 + w] V, [160] count; stride 162.
__global__ void k_node(const float* __restrict__ x, const float* __restrict__ Wss,
                       const float* __restrict__ Wsv, float* __restrict__ out, int N) {
    __shared__ float sx[8][128];
    const int warp = threadIdx.x >> 5, lane = threadIdx.x & 31;
    int n = blockIdx.x * 8 + warp;
    if (n >= N) return;

    const float4* xr = reinterpret_cast<const float4*>(x + (size_t)n * 128);
    reinterpret_cast<float4*>(&sx[warp][0])[lane] = xr[lane];
    __syncwarp();

    const float* na = g_nodeacc + (size_t)n * NASTRIDE;
    float inv = 1.0f / fmaxf(na[160], 1.0f);
    float ms  = na[lane] * inv;
    float mg  = na[32 + lane] * inv;
    float mv0 = na[64 + lane] * inv;
    float mv1 = na[96 + lane] * inv;
    float mv2 = na[128 + lane] * inv;

    float gs   = ms / (1.0f + expf(-ms));
    float gate = 1.0f / (1.0f + expf(-mg));
    float gv0 = mv0 * gate, gv1 = mv1 * gate, gv2 = mv2 * gate;

    float ds = 0.f, dv0 = 0.f, dv1 = 0.f, dv2 = 0.f;
    #pragma unroll 4
    for (int u = 0; u < 32; u++) {
        float su  = sx[warp][u];
        float vu0 = sx[warp][32 + 3 * u], vu1 = sx[warp][33 + 3 * u], vu2 = sx[warp][34 + 3 * u];
        float a = __ldg(&Wss[u * 32 + lane]);
        float b = __ldg(&Wsv[u * 32 + lane]);
        ds  = fmaf(su,  a, ds);
        dv0 = fmaf(vu0, b, dv0);
        dv1 = fmaf(vu1, b, dv1);
        dv2 = fmaf(vu2, b, dv2);
    }
    const float ism = 0.17677669529663687f;   // 1/sqrt(32)
    float hs  = gs  + ds  * ism;
    float hv0 = gv0 + dv0 * ism;
    float hv1 = gv1 + dv1 * ism;
    float hv2 = gv2 + dv2 * ism;

    out[(size_t)n * 64 + lane]      = sqrtf(hs * hs + 1e-12f);
    out[(size_t)n * 64 + 32 + lane] = sqrtf(hv0 * hv0 + hv1 * hv1 + hv2 * hv2 + 1e-12f);
}

// ---------------- launch ----------------
extern "C" void kernel_launch(void* const* d_in, const int* in_sizes, int n_in,
                              void* d_out, int out_size) {
    const float* x    = (const float*)d_in[0];
    const float* attr = (const float*)d_in[1];
    const float* len  = (const float*)d_in[2];
    const int*   src  = (const int*)d_in[3];
    const int*   dst  = (const int*)d_in[4];
    const float* Wfc1 = (const float*)d_in[5];
    const float* Wfc2 = (const float*)d_in[6];
    const float* Wss  = (const float*)d_in[7];
    const float* Wsv  = (const float*)d_in[8];
    float* out = (float*)d_out;

    int N = in_sizes[0] / 128;
    int E = in_sizes[2];

    cudaFuncSetAttribute(k_edge_mma, cudaFuncAttributeMaxDynamicSharedMemorySize, SMEM_BYTES);

    dim3 bgrid(KNOTS / 16, 28);
    k_build<<<bgrid, 256>>>(Wfc1, Wfc2, len, E);                 // #1 (B matrices + hist)
    k_scan<<<1, 32>>>();                                         // #2 (pad-32 scan + tiles)
    k_scatterzero<<<(E + 255) / 256, 256>>>(len, E, N * NASTRIDE);  // #3 (scatter + zero)
    k_edge_mma<<<NTILES, 256, SMEM_BYTES>>>(x, attr, len, src, dst);  // #4 (profiled)
    k_node<<<(N + 7) / 8, 256>>>(x, Wss, Wsv, out, N);           // #5
}

// round 13
// speedup vs baseline: 1.0291x; 1.0291x over previous
#include <cuda_runtime.h>
#include <cuda_fp16.h>
#include <math.h>

#define KNOTS 64
#define WCOLS 7168          // 7 paths * 32 u * 32 w
#define MAXN  4096
#define MAXE  32768
#define NCELLS 63           // cell_of in [0,62]
#define PERM_SZ (MAXE + 16 * 64)   // per-cell pad to mult of 16
#define NTILES  (PERM_SZ / 16)     // 2112
#define NASTRIDE 162        // even stride -> 8B-aligned red.v2 targets

// B layouts (halfs), rows padded for conflict-free ldmatrix
#define ST_SG 136           // K=128 + 8 pad
#define ST_V  200           // K=192 + 8 pad
#define BSG_CELL (64 * ST_SG)   // 8704 halfs
#define BV_CELL  (32 * ST_V)    // 6400 halfs

// ---------------- scratch (device globals; no allocation allowed) ----------------
__device__ __align__(16) __half g_Bsg[64 * BSG_CELL];   // [cell][n=64][k=128 pad 136]
__device__ __align__(16) __half g_Bv [64 * BV_CELL];    // [cell][n=32][k=192 pad 200]
__device__ float g_nodeacc[MAXN * NASTRIDE];
__device__ int   g_binCount[64];
__device__ int   g_binCursor[64];
__device__ int   g_perm[PERM_SZ];
__device__ int   g_tileCell[NTILES];

__device__ __forceinline__ int cell_of(float L) {
    float t = L * ((float)(KNOTS - 1) / 5.0f);
    int i = (int)floorf(t);
    if (i < 0) i = 0;
    if (i > KNOTS - 2) i = KNOTS - 2;
    return i;
}

__device__ __forceinline__ unsigned smaddr(const void* p) {
    return (unsigned)__cvta_generic_to_shared(p);
}
__device__ __forceinline__ void ldsm4(unsigned& a0, unsigned& a1, unsigned& a2, unsigned& a3,
                                      unsigned addr) {
    asm volatile("ldmatrix.sync.aligned.m8n8.x4.shared.b16 {%0,%1,%2,%3}, [%4];"
                 : "=r"(a0), "=r"(a1), "=r"(a2), "=r"(a3) : "r"(addr));
}
__device__ __forceinline__ void ldsm2(unsigned& b0, unsigned& b1, unsigned addr) {
    asm volatile("ldmatrix.sync.aligned.m8n8.x2.shared.b16 {%0,%1}, [%2];"
                 : "=r"(b0), "=r"(b1) : "r"(addr));
}
__device__ __forceinline__ void mma16816(float* c, unsigned a0, unsigned a1, unsigned a2,
                                         unsigned a3, unsigned b0, unsigned b1) {
    asm volatile(
        "mma.sync.aligned.m16n8k16.row.col.f32.f16.f16.f32 "
        "{%0,%1,%2,%3}, {%4,%5,%6,%7}, {%8,%9}, {%0,%1,%2,%3};\n"
        : "+f"(c[0]), "+f"(c[1]), "+f"(c[2]), "+f"(c[3])
        : "r"(a0), "r"(a1), "r"(a2), "r"(a3), "r"(b0), "r"(b1));
}
__device__ __forceinline__ void red2(float* p, float a, float b) {
    asm volatile("red.global.add.v2.f32 [%0], {%1, %2};" :: "l"(p), "f"(a), "f"(b) : "memory");
}

// ---------------- kernel 1: build per-cell B matrices + histogram ----------------
// Grid (4, 28), block 256: 16 knot-rows x 256 cols each.
__global__ void k_build(const float* __restrict__ Wfc1, const float* __restrict__ Wfc2,
                        const float* __restrict__ len, int E) {
    __shared__ float sm_h[64][17];
    __shared__ int   sm_hist[64];
    const int t = threadIdx.x;
    const int kbase = blockIdx.x * 16;
    const int col = blockIdx.y * 256 + t;

    if (t < 64) sm_hist[t] = 0;
    __syncthreads();

    {
        int gid = (blockIdx.y * gridDim.x + blockIdx.x) * 256 + t;
        int stride = gridDim.x * gridDim.y * 256;
        for (int e = gid; e < E; e += stride)
            atomicAdd(&sm_hist[cell_of(len[e])], 1);
    }

    for (int idx = t; idx < 16 * 64; idx += 256) {
        int kk = idx >> 6, c = idx & 63;
        float r = (float)(kbase + kk) * (5.0f / (float)(KNOTS - 1));
        float pre = 0.0f;
        #pragma unroll
        for (int j = 0; j < 8; j++) {
            float d = r - (float)j * (5.0f / 7.0f);
            float rad = expf(-d * d * 0.98f);
            pre += rad * Wfc1[j * 64 + c];
        }
        pre *= 0.35355339059327373f;                 // 1/sqrt(8)
        sm_h[c][kk] = pre / (1.0f + expf(-pre));     // silu
    }
    __syncthreads();

    if (t < 64 && sm_hist[t] > 0) atomicAdd(&g_binCount[t], sm_hist[t]);

    float acc[16];
    #pragma unroll
    for (int kk = 0; kk < 16; kk++) acc[kk] = 0.0f;
    #pragma unroll 4
    for (int c = 0; c < 64; c++) {
        float wv = __ldg(&Wfc2[c * WCOLS + col]);
        #pragma unroll
        for (int kk = 0; kk < 16; kk++) acc[kk] = fmaf(sm_h[c][kk], wv, acc[kk]);
    }
    float sc = (col < 4096) ? 0.015625f : 0.022097086912079608f;

    const int p = col >> 10, u = (col >> 5) & 31, w = col & 31;
    #pragma unroll
    for (int kk = 0; kk < 16; kk++) {
        __half hv = __float2half_rn(acc[kk] * sc);
        int row = kbase + kk;
        if (p < 4) {
            int n = (p >> 1) * 32 + w;         // S cols 0-31, G cols 32-63
            int kb = (p & 1) * 32 + u;         // feat*32 + u
            if (row <= 62) g_Bsg[(size_t)row * BSG_CELL + n * ST_SG + kb] = hv;        // knot0
            if (row >= 1)  g_Bsg[(size_t)(row - 1) * BSG_CELL + n * ST_SG + 64 + kb] = hv;  // knot1
        } else {
            int kb = (p - 4) * 32 + u;
            if (row <= 62) g_Bv[(size_t)row * BV_CELL + w * ST_V + kb] = hv;
            if (row >= 1)  g_Bv[(size_t)(row - 1) * BV_CELL + w * ST_V + 96 + kb] = hv;
        }
    }
}

// ---------------- kernel 2: scan (pad-16) + tile map + bin reset ----------------
__global__ void k_scan() {
    int t = threadIdx.x;   // 32
    int c0 = 2 * t, c1 = 2 * t + 1;
    int n0 = (c0 < NCELLS) ? g_binCount[c0] : 0;
    int n1 = (c1 < NCELLS) ? g_binCount[c1] : 0;
    int p0 = (n0 + 15) & ~15, p1 = (n1 + 15) & ~15;
    int s = p0 + p1;
    int x = s;
    #pragma unroll
    for (int o = 1; o < 32; o <<= 1) {
        int y = __shfl_up_sync(0xffffffffu, x, o);
        if (t >= o) x += y;
    }
    int base0 = x - s;
    int base1 = base0 + p0;
    g_binCursor[c0] = base0;
    g_binCursor[c1] = base1;
    for (int i = n0; i < p0; i++) g_perm[base0 + i] = -1;
    for (int i = n1; i < p1; i++) g_perm[base1 + i] = -1;
    for (int i = 0; i < (p0 >> 4); i++) g_tileCell[(base0 >> 4) + i] = c0;
    for (int i = 0; i < (p1 >> 4); i++) g_tileCell[(base1 >> 4) + i] = c1;
    int tot = __shfl_sync(0xffffffffu, x, 31);
    for (int i = (tot >> 4) + t; i < NTILES; i += 32) g_tileCell[i] = -1;
    g_binCount[c0] = 0;
    g_binCount[c1] = 0;
}

// ---------------- kernel 3: two-level scatter + nodeacc zeroing ----------------
__global__ void k_scatterzero(const float* __restrict__ len, int E, int accTotal) {
    __shared__ int sCnt[64];
    __shared__ int sBase[64];
    const int t = threadIdx.x;
    const int gid = blockIdx.x * 256 + t;

    if (t < 64) sCnt[t] = 0;

    for (int i = gid; i < accTotal; i += gridDim.x * 256) g_nodeacc[i] = 0.0f;
    __syncthreads();

    int e = -1, bin = 0, rank = 0;
    if (gid < E) {
        e = gid;
        bin = cell_of(len[e]);
        rank = atomicAdd(&sCnt[bin], 1);
    }
    __syncthreads();
    if (t < 64) sBase[t] = (sCnt[t] > 0) ? atomicAdd(&g_binCursor[t], sCnt[t]) : 0;
    __syncthreads();
    if (e >= 0) g_perm[sBase[bin] + rank] = e;
}

// ---------------- kernel 4 (profiled slot): tensor-core edge kernel ----------------
// CTA = 16 same-cell edges. 20 independent work items over 8 warps,
// ldmatrix fragment loads, red.global.add.v2.f32 epilogue. 4 CTAs/SM.
#define OFF_AV  2176
#define OFF_BSG 11776
#define OFF_BV  20480
#define SMEM_HALFS 26880
#define SMEM_BYTES (SMEM_HALFS * 2 + 128)

__global__ __launch_bounds__(256, 4) void k_edge_mma(
        const float* __restrict__ x, const float* __restrict__ attr,
        const float* __restrict__ len, const int* __restrict__ src,
        const int* __restrict__ dst) {
    extern __shared__ __align__(16) __half smh[];
    __half* sAsg = smh;
    __half* sAv  = smh + OFF_AV;
    __half* sBsg = smh + OFF_BSG;
    __half* sBv  = smh + OFF_BV;
    int* sEdge = (int*)(smh + SMEM_HALFS);
    int* sDst  = sEdge + 16;

    const int tile = blockIdx.x;
    const int cell = g_tileCell[tile];
    if (cell < 0) return;
    const int t = threadIdx.x;
    const int lane = t & 31, warp = t >> 5;

    // ---- stage B (coalesced) ----
    {
        const uint4* gb = (const uint4*)(g_Bsg + (size_t)cell * BSG_CELL);
        uint4* sb = (uint4*)sBsg;
        for (int i = t; i < BSG_CELL / 8; i += 256) sb[i] = gb[i];
        const uint4* gv = (const uint4*)(g_Bv + (size_t)cell * BV_CELL);
        uint4* sv = (uint4*)sBv;
        for (int i = t; i < BV_CELL / 8; i += 256) sv[i] = gv[i];
    }

    // ---- feature phase: thread t -> edge e = t>>4, u in {t&15, (t&15)+16} ----
    {
        const int e = t >> 4, u0 = t & 15;
        int eg = g_perm[tile * 16 + e];
        float f = 0.0f;
        float y0 = 0, y10 = 0, y11 = 0, y12 = 0;
        float M00 = 0, M01 = 0, M02 = 0, M10 = 0, M11 = 0, M12 = 0, M20 = 0, M21 = 0, M22 = 0;
        const float* xr = x;   // dummy
        if (eg >= 0) {
            float L = len[eg];
            float tp = L * ((float)(KNOTS - 1) / 5.0f) - (float)cell;
            f = fminf(fmaxf(tp, 0.0f), 1.0f);
            const float* ar = attr + eg * 9;
            y0 = ar[0]; y10 = ar[1]; y11 = ar[2]; y12 = ar[3];
            float y20 = ar[4], y21 = ar[5], y22 = ar[6], y23 = ar[7], y24 = ar[8];
            const float cA = 0.31622776601683794f;
            const float cB = 0.18257418583505536f;
            const float cC = 0.36514837167011072f;
            M00 = -cB * y22 + cA * y24;
            M01 =  cA * y20;  M02 = cA * y23;
            M10 =  cA * y20;  M11 = -cB * y22 - cA * y24;  M12 = cA * y21;
            M20 =  cA * y23;  M21 = cA * y21;              M22 = cC * y22;
            xr = x + (size_t)src[eg] * 128;
        }
        float g1 = 1.0f - f;
        if (u0 == 0) {
            sEdge[e] = eg;
            int dn = (eg >= 0) ? dst[eg] : 0;
            sDst[e] = dn;
            if (eg >= 0) atomicAdd(g_nodeacc + (size_t)dn * NASTRIDE + 160, 1.0f);
        }
        const float IS3 = 0.5773502691896258f;
        #pragma unroll
        for (int half_ = 0; half_ < 2; half_++) {
            int u = u0 + half_ * 16;
            float F[11];
            #pragma unroll
            for (int k = 0; k < 11; k++) F[k] = 0.0f;
            if (eg >= 0) {
                float sj = xr[u];
                float v0 = xr[32 + 3 * u], v1 = xr[33 + 3 * u], v2 = xr[34 + 3 * u];
                F[0] = sj * y0;
                F[1] = (v0 * y10 + v1 * y11 + v2 * y12) * IS3;
                float sy = sj * IS3;
                F[2] = sy * y10; F[3] = sy * y11; F[4] = sy * y12;
                float yv = y0 * IS3;
                F[5] = v0 * yv; F[6] = v1 * yv; F[7] = v2 * yv;
                F[8]  = v0 * M00 + v1 * M10 + v2 * M20;
                F[9]  = v0 * M01 + v1 * M11 + v2 * M21;
                F[10] = v0 * M02 + v1 * M12 + v2 * M22;
            }
            __half* asg = sAsg + e * ST_SG;
            asg[u]      = __float2half_rn(F[0] * g1);
            asg[32 + u] = __float2half_rn(F[1] * g1);
            asg[64 + u] = __float2half_rn(F[0] * f);
            asg[96 + u] = __float2half_rn(F[1] * f);
            #pragma unroll
            for (int kc = 0; kc < 3; kc++) {
                __half* av = sAv + (kc * 16 + e) * ST_V;
                av[u]        = __float2half_rn(F[2 + kc] * g1);   // t01 -> path4
                av[32 + u]   = __float2half_rn(F[5 + kc] * g1);   // t10 -> path5
                av[64 + u]   = __float2half_rn(F[8 + kc] * g1);   // t12 -> path6
                av[96 + u]   = __float2half_rn(F[2 + kc] * f);
                av[128 + u]  = __float2half_rn(F[5 + kc] * f);
                av[160 + u]  = __float2half_rn(F[8 + kc] * f);
            }
        }
    }
    __syncthreads();

    // ---- MMA phase: 20 work items (8 SG n-tiles, 12 V (kcomp,n)-tiles) over 8 warps ----
    const int l15 = lane & 15;
    const int aoff = (lane >> 4) * 8;          // A fragment col-half select
    const int boff = ((l15 >> 3) & 1) * 8;     // B fragment col-half select
    const int bn   = l15 & 7;                  // B fragment row-in-tile

    for (int item = warp; item < 20; item += 8) {
        float c[4] = {0.f, 0.f, 0.f, 0.f};
        const __half *A, *B;
        int K, stA, nb;
        int isV = (item >= 8);
        int kcomp = 0;
        if (!isV) {
            A = sAsg; B = sBsg; K = 8; stA = ST_SG; nb = item * 8;
        } else {
            int idx = item - 8;
            kcomp = idx >> 2;
            int nt = idx & 3;
            A = sAv + kcomp * 16 * ST_V; B = sBv; K = 12; stA = ST_V; nb = nt * 8;
        }
        const int stB = stA;
        const unsigned aBase = smaddr(A + l15 * stA + aoff);
        const unsigned bBase = smaddr(B + (nb + bn) * stB + boff);
        for (int ks = 0; ks < K; ks++) {
            int kb2 = ks * 32;   // ks*16 halfs = ks*32 bytes
            unsigned a0, a1, a2, a3, b0, b1;
            ldsm4(a0, a1, a2, a3, aBase + kb2);
            ldsm2(b0, b1, bBase + kb2);
            mma16816(c, a0, a1, a2, a3, b0, b1);
        }
        // epilogue: rows r0, r0+8 = edges; cols cp, cp+1 contiguous -> red2
        const int r0 = lane >> 2, cp = (lane & 3) * 2;
        int ed0 = sEdge[r0], ed1 = sEdge[r0 + 8];
        int col = (!isV) ? (item * 8 + cp) : (64 + kcomp * 32 + nb + cp);
        if (ed0 >= 0) red2(g_nodeacc + (size_t)sDst[r0] * NASTRIDE + col, c[0], c[1]);
        if (ed1 >= 0) red2(g_nodeacc + (size_t)sDst[r0 + 8] * NASTRIDE + col, c[2], c[3]);
    }
}

// ---------------- kernel 5: mean, gating, self-connection, norms ----------------
// nodeacc layout: [0:32) S, [32:64) G, [64+kcomp*32 + w] V, [160] count; stride 162.
__global__ void k_node(const float* __restrict__ x, const float* __restrict__ Wss,
                       const float* __restrict__ Wsv, float* __restrict__ out, int N) {
    __shared__ float sx[8][128];
    const int warp = threadIdx.x >> 5, lane = threadIdx.x & 31;
    int n = blockIdx.x * 8 + warp;
    if (n >= N) return;

    const float4* xr = reinterpret_cast<const float4*>(x + (size_t)n * 128);
    reinterpret_cast<float4*>(&sx[warp][0])[lane] = xr[lane];
    __syncwarp();

    const float* na = g_nodeacc + (size_t)n * NASTRIDE;
    float inv = 1.0f / fmaxf(na[160], 1.0f);
    float ms  = na[lane] * inv;
    float mg  = na[32 + lane] * inv;
    float mv0 = na[64 + lane] * inv;
    float mv1 = na[96 + lane] * inv;
    float mv2 = na[128 + lane] * inv;

    float gs   = ms / (1.0f + expf(-ms));
    float gate = 1.0f / (1.0f + expf(-mg));
    float gv0 = mv0 * gate, gv1 = mv1 * gate, gv2 = mv2 * gate;

    float ds = 0.f, dv0 = 0.f, dv1 = 0.f, dv2 = 0.f;
    #pragma unroll 4
    for (int u = 0; u < 32; u++) {
        float su  = sx[warp][u];
        float vu0 = sx[warp][32 + 3 * u], vu1 = sx[warp][33 + 3 * u], vu2 = sx[warp][34 + 3 * u];
        float a = __ldg(&Wss[u * 32 + lane]);
        float b = __ldg(&Wsv[u * 32 + lane]);
        ds  = fmaf(su,  a, ds);
        dv0 = fmaf(vu0, b, dv0);
        dv1 = fmaf(vu1, b, dv1);
        dv2 = fmaf(vu2, b, dv2);
    }
    const float ism = 0.17677669529663687f;   // 1/sqrt(32)
    float hs  = gs  + ds  * ism;
    float hv0 = gv0 + dv0 * ism;
    float hv1 = gv1 + dv1 * ism;
    float hv2 = gv2 + dv2 * ism;

    out[(size_t)n * 64 + lane]      = sqrtf(hs * hs + 1e-12f);
    out[(size_t)n * 64 + 32 + lane] = sqrtf(hv0 * hv0 + hv1 * hv1 + hv2 * hv2 + 1e-12f);
}

// ---------------- launch ----------------
extern "C" void kernel_launch(void* const* d_in, const int* in_sizes, int n_in,
                              void* d_out, int out_size) {
    const float* x    = (const float*)d_in[0];
    const float* attr = (const float*)d_in[1];
    const float* len  = (const float*)d_in[2];
    const int*   src  = (const int*)d_in[3];
    const int*   dst  = (const int*)d_in[4];
    const float* Wfc1 = (const float*)d_in[5];
    const float* Wfc2 = (const float*)d_in[6];
    const float* Wss  = (const float*)d_in[7];
    const float* Wsv  = (const float*)d_in[8];
    float* out = (float*)d_out;

    int N = in_sizes[0] / 128;
    int E = in_sizes[2];

    cudaFuncSetAttribute(k_edge_mma, cudaFuncAttributeMaxDynamicSharedMemorySize, SMEM_BYTES);

    dim3 bgrid(KNOTS / 16, 28);
    k_build<<<bgrid, 256>>>(Wfc1, Wfc2, len, E);                 // #1 (B matrices + hist)
    k_scan<<<1, 32>>>();                                         // #2 (pad-16 scan + tiles)
    k_scatterzero<<<(E + 255) / 256, 256>>>(len, E, N * NASTRIDE);  // #3 (scatter + zero)
    k_edge_mma<<<NTILES, 256, SMEM_BYTES>>>(x, attr, len, src, dst);  // #4 (profiled)
    k_node<<<(N + 7) / 8, 256>>>(x, Wss, Wsv, out, N);           // #5
}

// round 14
// speedup vs baseline: 1.1570x; 1.1242x over previous
#include <cuda_runtime.h>
#include <cuda_fp16.h>
#include <math.h>

#define KNOTS 64
#define WCOLS 7168          // 7 paths * 32 u * 32 w
#define MAXN  4096
#define MAXE  32768
#define NCELLS 63           // cell_of in [0,62]
#define PERM_SZ (MAXE + 16 * 64)   // per-cell pad to mult of 16
#define NTILES  (PERM_SZ / 16)     // 2112
#define NASTRIDE 162        // even stride -> 8B-aligned red.v2 targets

// B layouts (halfs), rows padded for conflict-free ldmatrix
#define ST_SG 136           // K=128 + 8 pad
#define ST_V  200           // K=192 + 8 pad
#define BSG_CELL (64 * ST_SG)   // 8704 halfs
#define BV_CELL  (32 * ST_V)    // 6400 halfs

// ---------------- scratch (device globals; no allocation allowed) ----------------
__device__ __align__(16) __half g_Bsg[64 * BSG_CELL];   // [cell][n=64][k=128 pad 136]
__device__ __align__(16) __half g_Bv [64 * BV_CELL];    // [cell][n=32][k=192 pad 200]
__device__ float g_nodeacc[MAXN * NASTRIDE];
__device__ int   g_binCount[64];
__device__ int   g_binCursor[64];
__device__ int   g_perm[PERM_SZ];
__device__ int   g_tileCell[NTILES];
__device__ int   g_buildDone;     // zero-init; self-resetting

__device__ __forceinline__ int cell_of(float L) {
    float t = L * ((float)(KNOTS - 1) / 5.0f);
    int i = (int)floorf(t);
    if (i < 0) i = 0;
    if (i > KNOTS - 2) i = KNOTS - 2;
    return i;
}

__device__ __forceinline__ unsigned smaddr(const void* p) {
    return (unsigned)__cvta_generic_to_shared(p);
}
__device__ __forceinline__ void ldsm4(unsigned& a0, unsigned& a1, unsigned& a2, unsigned& a3,
                                      unsigned addr) {
    asm volatile("ldmatrix.sync.aligned.m8n8.x4.shared.b16 {%0,%1,%2,%3}, [%4];"
                 : "=r"(a0), "=r"(a1), "=r"(a2), "=r"(a3) : "r"(addr));
}
__device__ __forceinline__ void ldsm2(unsigned& b0, unsigned& b1, unsigned addr) {
    asm volatile("ldmatrix.sync.aligned.m8n8.x2.shared.b16 {%0,%1}, [%2];"
                 : "=r"(b0), "=r"(b1) : "r"(addr));
}
__device__ __forceinline__ void mma16816(float* c, unsigned a0, unsigned a1, unsigned a2,
                                         unsigned a3, unsigned b0, unsigned b1) {
    asm volatile(
        "mma.sync.aligned.m16n8k16.row.col.f32.f16.f16.f32 "
        "{%0,%1,%2,%3}, {%4,%5,%6,%7}, {%8,%9}, {%0,%1,%2,%3};\n"
        : "+f"(c[0]), "+f"(c[1]), "+f"(c[2]), "+f"(c[3])
        : "r"(a0), "r"(a1), "r"(a2), "r"(a3), "r"(b0), "r"(b1));
}
__device__ __forceinline__ void red2(float* p, float a, float b) {
    asm volatile("red.global.add.v2.f32 [%0], {%1, %2};" :: "l"(p), "f"(a), "f"(b) : "memory");
}

// ---------------- kernel 1: build per-cell B matrices + histogram + (last block) scan ----
// Grid (4, 28), block 256: 16 knot-rows x 256 cols each. p = by>>2 const per block,
// u in [ub, ub+8) with ub = (by&3)*8, w = 0..31. Coalesced 16B table stores.
__global__ void k_build(const float* __restrict__ Wfc1, const float* __restrict__ Wfc2,
                        const float* __restrict__ len, int E) {
    __shared__ float sm_h[64][17];
    __shared__ int   sm_hist[64];
    __shared__ __half sm_buf[16][256];   // [kk][u_local*32+w]
    __shared__ int   sm_last;
    const int t = threadIdx.x;
    const int kbase = blockIdx.x * 16;
    const int col = blockIdx.y * 256 + t;

    if (t < 64) sm_hist[t] = 0;
    __syncthreads();

    {
        int gid = (blockIdx.y * gridDim.x + blockIdx.x) * 256 + t;
        int stride = gridDim.x * gridDim.y * 256;
        for (int e = gid; e < E; e += stride)
            atomicAdd(&sm_hist[cell_of(len[e])], 1);
    }

    for (int idx = t; idx < 16 * 64; idx += 256) {
        int kk = idx >> 6, c = idx & 63;
        float r = (float)(kbase + kk) * (5.0f / (float)(KNOTS - 1));
        float pre = 0.0f;
        #pragma unroll
        for (int j = 0; j < 8; j++) {
            float d = r - (float)j * (5.0f / 7.0f);
            float rad = expf(-d * d * 0.98f);
            pre += rad * Wfc1[j * 64 + c];
        }
        pre *= 0.35355339059327373f;                 // 1/sqrt(8)
        sm_h[c][kk] = pre / (1.0f + expf(-pre));     // silu
    }
    __syncthreads();

    if (t < 64 && sm_hist[t] > 0) atomicAdd(&g_binCount[t], sm_hist[t]);

    float acc[16];
    #pragma unroll
    for (int kk = 0; kk < 16; kk++) acc[kk] = 0.0f;
    #pragma unroll 4
    for (int c = 0; c < 64; c++) {
        float wv = __ldg(&Wfc2[c * WCOLS + col]);
        #pragma unroll
        for (int kk = 0; kk < 16; kk++) acc[kk] = fmaf(sm_h[c][kk], wv, acc[kk]);
    }
    const int p = blockIdx.y >> 2;
    const int ub = (blockIdx.y & 3) * 8;
    float sc = (p < 4) ? 0.015625f : 0.022097086912079608f;
    #pragma unroll
    for (int kk = 0; kk < 16; kk++)
        sm_buf[kk][t] = __float2half_rn(acc[kk] * sc);
    __syncthreads();

    // coalesced writeout: work item = (kk, w); gather 8 u-contiguous halfs -> 16B store
    for (int idx = t; idx < 16 * 32; idx += 256) {
        const int kk = idx >> 5, w = idx & 31;
        unsigned short h[8];
        #pragma unroll
        for (int ul = 0; ul < 8; ul++)
            h[ul] = __half_as_ushort(sm_buf[kk][ul * 32 + w]);
        uint4 v = *reinterpret_cast<uint4*>(h);
        const int row = kbase + kk;
        if (p < 4) {
            int n = (p >> 1) * 32 + w;
            int kb0 = (p & 1) * 32 + ub;
            if (row <= 62)
                *reinterpret_cast<uint4*>(&g_Bsg[(size_t)row * BSG_CELL + n * ST_SG + kb0]) = v;
            if (row >= 1)
                *reinterpret_cast<uint4*>(&g_Bsg[(size_t)(row - 1) * BSG_CELL + n * ST_SG + 64 + kb0]) = v;
        } else {
            int kb0 = (p - 4) * 32 + ub;
            if (row <= 62)
                *reinterpret_cast<uint4*>(&g_Bv[(size_t)row * BV_CELL + w * ST_V + kb0]) = v;
            if (row >= 1)
                *reinterpret_cast<uint4*>(&g_Bv[(size_t)(row - 1) * BV_CELL + w * ST_V + 96 + kb0]) = v;
        }
    }

    // ---- last-block scan (pad-16) + tile map + resets ----
    __threadfence();
    __syncthreads();
    if (t == 0) {
        int total = gridDim.x * gridDim.y;
        sm_last = (atomicAdd(&g_buildDone, 1) + 1 == total) ? 1 : 0;
    }
    __syncthreads();
    if (sm_last && t < 32) {
        int c0 = 2 * t, c1 = 2 * t + 1;
        int n0 = (c0 < NCELLS) ? g_binCount[c0] : 0;
        int n1 = (c1 < NCELLS) ? g_binCount[c1] : 0;
        int p0 = (n0 + 15) & ~15, p1 = (n1 + 15) & ~15;
        int s = p0 + p1;
        int x = s;
        #pragma unroll
        for (int o = 1; o < 32; o <<= 1) {
            int y = __shfl_up_sync(0xffffffffu, x, o);
            if (t >= o) x += y;
        }
        int base0 = x - s;
        int base1 = base0 + p0;
        g_binCursor[c0] = base0;
        g_binCursor[c1] = base1;
        for (int i = n0; i < p0; i++) g_perm[base0 + i] = -1;
        for (int i = n1; i < p1; i++) g_perm[base1 + i] = -1;
        for (int i = 0; i < (p0 >> 4); i++) g_tileCell[(base0 >> 4) + i] = c0;
        for (int i = 0; i < (p1 >> 4); i++) g_tileCell[(base1 >> 4) + i] = c1;
        int tot = __shfl_sync(0xffffffffu, x, 31);
        for (int i = (tot >> 4) + t; i < NTILES; i += 32) g_tileCell[i] = -1;
        g_binCount[c0] = 0;
        g_binCount[c1] = 0;
        if (t == 0) g_buildDone = 0;   // reset for graph replay
    }
}

// ---------------- kernel 2: two-level scatter + nodeacc zeroing ----------------
__global__ void k_scatterzero(const float* __restrict__ len, int E, int accTotal) {
    __shared__ int sCnt[64];
    __shared__ int sBase[64];
    const int t = threadIdx.x;
    const int gid = blockIdx.x * 256 + t;

    if (t < 64) sCnt[t] = 0;

    for (int i = gid; i < accTotal; i += gridDim.x * 256) g_nodeacc[i] = 0.0f;
    __syncthreads();

    int e = -1, bin = 0, rank = 0;
    if (gid < E) {
        e = gid;
        bin = cell_of(len[e]);
        rank = atomicAdd(&sCnt[bin], 1);
    }
    __syncthreads();
    if (t < 64) sBase[t] = (sCnt[t] > 0) ? atomicAdd(&g_binCursor[t], sCnt[t]) : 0;
    __syncthreads();
    if (e >= 0) g_perm[sBase[bin] + rank] = e;
}

// ---------------- kernel 3 (profiled slot moves to #3): tensor-core edge kernel ----------------
// CTA = 16 same-cell edges. 20 independent work items over 8 warps,
// ldmatrix fragment loads, red.global.add.v2.f32 epilogue.
#define OFF_AV  2176
#define OFF_BSG 11776
#define OFF_BV  20480
#define SMEM_HALFS 26880
#define SMEM_BYTES (SMEM_HALFS * 2 + 128)

__global__ __launch_bounds__(256, 4) void k_edge_mma(
        const float* __restrict__ x, const float* __restrict__ attr,
        const float* __restrict__ len, const int* __restrict__ src,
        const int* __restrict__ dst) {
    extern __shared__ __align__(16) __half smh[];
    __half* sAsg = smh;
    __half* sAv  = smh + OFF_AV;
    __half* sBsg = smh + OFF_BSG;
    __half* sBv  = smh + OFF_BV;
    int* sEdge = (int*)(smh + SMEM_HALFS);
    int* sDst  = sEdge + 16;

    const int tile = blockIdx.x;
    const int cell = g_tileCell[tile];
    if (cell < 0) return;
    const int t = threadIdx.x;
    const int lane = t & 31, warp = t >> 5;

    // ---- stage B (coalesced) ----
    {
        const uint4* gb = (const uint4*)(g_Bsg + (size_t)cell * BSG_CELL);
        uint4* sb = (uint4*)sBsg;
        for (int i = t; i < BSG_CELL / 8; i += 256) sb[i] = gb[i];
        const uint4* gv = (const uint4*)(g_Bv + (size_t)cell * BV_CELL);
        uint4* sv = (uint4*)sBv;
        for (int i = t; i < BV_CELL / 8; i += 256) sv[i] = gv[i];
    }

    // ---- feature phase: thread t -> edge e = t>>4, u in {t&15, (t&15)+16} ----
    {
        const int e = t >> 4, u0 = t & 15;
        int eg = g_perm[tile * 16 + e];
        float f = 0.0f;
        float y0 = 0, y10 = 0, y11 = 0, y12 = 0;
        float M00 = 0, M01 = 0, M02 = 0, M10 = 0, M11 = 0, M12 = 0, M20 = 0, M21 = 0, M22 = 0;
        const float* xr = x;   // dummy
        if (eg >= 0) {
            float L = len[eg];
            float tp = L * ((float)(KNOTS - 1) / 5.0f) - (float)cell;
            f = fminf(fmaxf(tp, 0.0f), 1.0f);
            const float* ar = attr + eg * 9;
            y0 = ar[0]; y10 = ar[1]; y11 = ar[2]; y12 = ar[3];
            float y20 = ar[4], y21 = ar[5], y22 = ar[6], y23 = ar[7], y24 = ar[8];
            const float cA = 0.31622776601683794f;
            const float cB = 0.18257418583505536f;
            const float cC = 0.36514837167011072f;
            M00 = -cB * y22 + cA * y24;
            M01 =  cA * y20;  M02 = cA * y23;
            M10 =  cA * y20;  M11 = -cB * y22 - cA * y24;  M12 = cA * y21;
            M20 =  cA * y23;  M21 = cA * y21;              M22 = cC * y22;
            xr = x + (size_t)src[eg] * 128;
        }
        float g1 = 1.0f - f;
        if (u0 == 0) {
            sEdge[e] = eg;
            int dn = (eg >= 0) ? dst[eg] : 0;
            sDst[e] = dn;
            if (eg >= 0) atomicAdd(g_nodeacc + (size_t)dn * NASTRIDE + 160, 1.0f);
        }
        const float IS3 = 0.5773502691896258f;
        #pragma unroll
        for (int half_ = 0; half_ < 2; half_++) {
            int u = u0 + half_ * 16;
            float F[11];
            #pragma unroll
            for (int k = 0; k < 11; k++) F[k] = 0.0f;
            if (eg >= 0) {
                float sj = xr[u];
                float v0 = xr[32 + 3 * u], v1 = xr[33 + 3 * u], v2 = xr[34 + 3 * u];
                F[0] = sj * y0;
                F[1] = (v0 * y10 + v1 * y11 + v2 * y12) * IS3;
                float sy = sj * IS3;
                F[2] = sy * y10; F[3] = sy * y11; F[4] = sy * y12;
                float yv = y0 * IS3;
                F[5] = v0 * yv; F[6] = v1 * yv; F[7] = v2 * yv;
                F[8]  = v0 * M00 + v1 * M10 + v2 * M20;
                F[9]  = v0 * M01 + v1 * M11 + v2 * M21;
                F[10] = v0 * M02 + v1 * M12 + v2 * M22;
            }
            __half* asg = sAsg + e * ST_SG;
            asg[u]      = __float2half_rn(F[0] * g1);
            asg[32 + u] = __float2half_rn(F[1] * g1);
            asg[64 + u] = __float2half_rn(F[0] * f);
            asg[96 + u] = __float2half_rn(F[1] * f);
            #pragma unroll
            for (int kc = 0; kc < 3; kc++) {
                __half* av = sAv + (kc * 16 + e) * ST_V;
                av[u]        = __float2half_rn(F[2 + kc] * g1);   // t01 -> path4
                av[32 + u]   = __float2half_rn(F[5 + kc] * g1);   // t10 -> path5
                av[64 + u]   = __float2half_rn(F[8 + kc] * g1);   // t12 -> path6
                av[96 + u]   = __float2half_rn(F[2 + kc] * f);
                av[128 + u]  = __float2half_rn(F[5 + kc] * f);
                av[160 + u]  = __float2half_rn(F[8 + kc] * f);
            }
        }
    }
    __syncthreads();

    // ---- MMA phase: 20 work items (8 SG n-tiles, 12 V (kcomp,n)-tiles) over 8 warps ----
    const int l15 = lane & 15;
    const int aoff = (lane >> 4) * 8;          // A fragment col-half select
    const int boff = ((l15 >> 3) & 1) * 8;     // B fragment col-half select
    const int bn   = l15 & 7;                  // B fragment row-in-tile

    for (int item = warp; item < 20; item += 8) {
        float c[4] = {0.f, 0.f, 0.f, 0.f};
        const __half *A, *B;
        int K, stA, nb;
        int isV = (item >= 8);
        int kcomp = 0;
        if (!isV) {
            A = sAsg; B = sBsg; K = 8; stA = ST_SG; nb = item * 8;
        } else {
            int idx = item - 8;
            kcomp = idx >> 2;
            int nt = idx & 3;
            A = sAv + kcomp * 16 * ST_V; B = sBv; K = 12; stA = ST_V; nb = nt * 8;
        }
        const int stB = stA;
        const unsigned aBase = smaddr(A + l15 * stA + aoff);
        const unsigned bBase = smaddr(B + (nb + bn) * stB + boff);
        for (int ks = 0; ks < K; ks++) {
            int kb2 = ks * 32;   // ks*16 halfs = ks*32 bytes
            unsigned a0, a1, a2, a3, b0, b1;
            ldsm4(a0, a1, a2, a3, aBase + kb2);
            ldsm2(b0, b1, bBase + kb2);
            mma16816(c, a0, a1, a2, a3, b0, b1);
        }
        // epilogue: rows r0, r0+8 = edges; cols cp, cp+1 contiguous -> red2
        const int r0 = lane >> 2, cp = (lane & 3) * 2;
        int ed0 = sEdge[r0], ed1 = sEdge[r0 + 8];
        int col = (!isV) ? (item * 8 + cp) : (64 + kcomp * 32 + nb + cp);
        if (ed0 >= 0) red2(g_nodeacc + (size_t)sDst[r0] * NASTRIDE + col, c[0], c[1]);
        if (ed1 >= 0) red2(g_nodeacc + (size_t)sDst[r0 + 8] * NASTRIDE + col, c[2], c[3]);
    }
}

// ---------------- kernel 4: mean, gating, self-connection, norms ----------------
// nodeacc layout: [0:32) S, [32:64) G, [64+kcomp*32 + w] V, [160] count; stride 162.
__global__ void k_node(const float* __restrict__ x, const float* __restrict__ Wss,
                       const float* __restrict__ Wsv, float* __restrict__ out, int N) {
    __shared__ float sx[8][128];
    const int warp = threadIdx.x >> 5, lane = threadIdx.x & 31;
    int n = blockIdx.x * 8 + warp;
    if (n >= N) return;

    const float4* xr = reinterpret_cast<const float4*>(x + (size_t)n * 128);
    reinterpret_cast<float4*>(&sx[warp][0])[lane] = xr[lane];
    __syncwarp();

    const float* na = g_nodeacc + (size_t)n * NASTRIDE;
    float inv = 1.0f / fmaxf(na[160], 1.0f);
    float ms  = na[lane] * inv;
    float mg  = na[32 + lane] * inv;
    float mv0 = na[64 + lane] * inv;
    float mv1 = na[96 + lane] * inv;
    float mv2 = na[128 + lane] * inv;

    float gs   = ms / (1.0f + expf(-ms));
    float gate = 1.0f / (1.0f + expf(-mg));
    float gv0 = mv0 * gate, gv1 = mv1 * gate, gv2 = mv2 * gate;

    float ds = 0.f, dv0 = 0.f, dv1 = 0.f, dv2 = 0.f;
    #pragma unroll 4
    for (int u = 0; u < 32; u++) {
        float su  = sx[warp][u];
        float vu0 = sx[warp][32 + 3 * u], vu1 = sx[warp][33 + 3 * u], vu2 = sx[warp][34 + 3 * u];
        float a = __ldg(&Wss[u * 32 + lane]);
        float b = __ldg(&Wsv[u * 32 + lane]);
        ds  = fmaf(su,  a, ds);
        dv0 = fmaf(vu0, b, dv0);
        dv1 = fmaf(vu1, b, dv1);
        dv2 = fmaf(vu2, b, dv2);
    }
    const float ism = 0.17677669529663687f;   // 1/sqrt(32)
    float hs  = gs  + ds  * ism;
    float hv0 = gv0 + dv0 * ism;
    float hv1 = gv1 + dv1 * ism;
    float hv2 = gv2 + dv2 * ism;

    out[(size_t)n * 64 + lane]      = sqrtf(hs * hs + 1e-12f);
    out[(size_t)n * 64 + 32 + lane] = sqrtf(hv0 * hv0 + hv1 * hv1 + hv2 * hv2 + 1e-12f);
}

// ---------------- launch ----------------
extern "C" void kernel_launch(void* const* d_in, const int* in_sizes, int n_in,
                              void* d_out, int out_size) {
    const float* x    = (const float*)d_in[0];
    const float* attr = (const float*)d_in[1];
    const float* len  = (const float*)d_in[2];
    const int*   src  = (const int*)d_in[3];
    const int*   dst  = (const int*)d_in[4];
    const float* Wfc1 = (const float*)d_in[5];
    const float* Wfc2 = (const float*)d_in[6];
    const float* Wss  = (const float*)d_in[7];
    const float* Wsv  = (const float*)d_in[8];
    float* out = (float*)d_out;

    int N = in_sizes[0] / 128;
    int E = in_sizes[2];

    cudaFuncSetAttribute(k_edge_mma, cudaFuncAttributeMaxDynamicSharedMemorySize, SMEM_BYTES);

    dim3 bgrid(KNOTS / 16, 28);
    k_build<<<bgrid, 256>>>(Wfc1, Wfc2, len, E);                 // #1 (B + hist + scan)
    k_scatterzero<<<(E + 255) / 256, 256>>>(len, E, N * NASTRIDE);  // #2 (scatter + zero)
    k_edge_mma<<<NTILES, 256, SMEM_BYTES>>>(x, attr, len, src, dst);  // #3
    k_node<<<(N + 7) / 8, 256>>>(x, Wss, Wsv, out, N);           // #4
}

// round 15
// speedup vs baseline: 1.1780x; 1.0182x over previous
#include <cuda_runtime.h>
#include <cuda_fp16.h>
#include <math.h>

#define KNOTS 64
#define WCOLS 7168          // 7 paths * 32 u * 32 w
#define MAXN  4096
#define MAXE  32768
#define NCELLS 63           // cell_of in [0,62]
#define PERM_SZ (MAXE + 16 * 64)   // per-cell pad to mult of 16
#define NTILES  (PERM_SZ / 16)     // 2112
#define NASTRIDE 162        // even stride -> 8B-aligned red.v2 targets

// B layouts (halfs), rows padded for conflict-free ldmatrix
#define ST_SG 136           // K=128 + 8 pad
#define ST_V  200           // K=192 + 8 pad
#define BSG_CELL (64 * ST_SG)   // 8704 halfs
#define BV_CELL  (32 * ST_V)    // 6400 halfs

// ---------------- scratch (device globals; no allocation allowed) ----------------
__device__ __align__(16) __half g_Bsg[64 * BSG_CELL];   // [cell][n=64][k=128 pad 136]
__device__ __align__(16) __half g_Bv [64 * BV_CELL];    // [cell][n=32][k=192 pad 200]
__device__ float g_nodeacc[MAXN * NASTRIDE];
__device__ int   g_binCount[64];
__device__ int   g_binCursor[64];
__device__ int   g_perm[PERM_SZ];
__device__ int   g_tileCell[NTILES];
__device__ int   g_buildDone;     // zero-init; self-resetting

__device__ __forceinline__ int cell_of(float L) {
    float t = L * ((float)(KNOTS - 1) / 5.0f);
    int i = (int)floorf(t);
    if (i < 0) i = 0;
    if (i > KNOTS - 2) i = KNOTS - 2;
    return i;
}

__device__ __forceinline__ unsigned smaddr(const void* p) {
    return (unsigned)__cvta_generic_to_shared(p);
}
__device__ __forceinline__ void ldsm4(unsigned& a0, unsigned& a1, unsigned& a2, unsigned& a3,
                                      unsigned addr) {
    asm volatile("ldmatrix.sync.aligned.m8n8.x4.shared.b16 {%0,%1,%2,%3}, [%4];"
                 : "=r"(a0), "=r"(a1), "=r"(a2), "=r"(a3) : "r"(addr));
}
__device__ __forceinline__ void ldsm2(unsigned& b0, unsigned& b1, unsigned addr) {
    asm volatile("ldmatrix.sync.aligned.m8n8.x2.shared.b16 {%0,%1}, [%2];"
                 : "=r"(b0), "=r"(b1) : "r"(addr));
}
__device__ __forceinline__ void mma16816(float* c, unsigned a0, unsigned a1, unsigned a2,
                                         unsigned a3, unsigned b0, unsigned b1) {
    asm volatile(
        "mma.sync.aligned.m16n8k16.row.col.f32.f16.f16.f32 "
        "{%0,%1,%2,%3}, {%4,%5,%6,%7}, {%8,%9}, {%0,%1,%2,%3};\n"
        : "+f"(c[0]), "+f"(c[1]), "+f"(c[2]), "+f"(c[3])
        : "r"(a0), "r"(a1), "r"(a2), "r"(a3), "r"(b0), "r"(b1));
}
__device__ __forceinline__ void red2(float* p, float a, float b) {
    asm volatile("red.global.add.v2.f32 [%0], {%1, %2};" :: "l"(p), "f"(a), "f"(b) : "memory");
}

// ---------------- kernel 1: build per-cell B matrices + histogram + (last block) scan ----
// Grid (4, 28), block 256: 16 knot-rows x 256 cols each. p = by>>2 const per block,
// u in [ub, ub+8) with ub = (by&3)*8, w = 0..31. Coalesced 16B table stores.
__global__ void k_build(const float* __restrict__ Wfc1, const float* __restrict__ Wfc2,
                        const float* __restrict__ len, int E) {
    __shared__ float sm_h[64][17];
    __shared__ int   sm_hist[64];
    __shared__ __half sm_buf[16][256];   // [kk][u_local*32+w]
    __shared__ int   sm_last;
    const int t = threadIdx.x;
    const int kbase = blockIdx.x * 16;
    const int col = blockIdx.y * 256 + t;

    if (t < 64) sm_hist[t] = 0;
    __syncthreads();

    {
        int gid = (blockIdx.y * gridDim.x + blockIdx.x) * 256 + t;
        int stride = gridDim.x * gridDim.y * 256;
        for (int e = gid; e < E; e += stride)
            atomicAdd(&sm_hist[cell_of(len[e])], 1);
    }

    for (int idx = t; idx < 16 * 64; idx += 256) {
        int kk = idx >> 6, c = idx & 63;
        float r = (float)(kbase + kk) * (5.0f / (float)(KNOTS - 1));
        float pre = 0.0f;
        #pragma unroll
        for (int j = 0; j < 8; j++) {
            float d = r - (float)j * (5.0f / 7.0f);
            float rad = expf(-d * d * 0.98f);
            pre += rad * Wfc1[j * 64 + c];
        }
        pre *= 0.35355339059327373f;                 // 1/sqrt(8)
        sm_h[c][kk] = pre / (1.0f + expf(-pre));     // silu
    }
    __syncthreads();

    if (t < 64 && sm_hist[t] > 0) atomicAdd(&g_binCount[t], sm_hist[t]);

    float acc[16];
    #pragma unroll
    for (int kk = 0; kk < 16; kk++) acc[kk] = 0.0f;
    #pragma unroll 4
    for (int c = 0; c < 64; c++) {
        float wv = __ldg(&Wfc2[c * WCOLS + col]);
        #pragma unroll
        for (int kk = 0; kk < 16; kk++) acc[kk] = fmaf(sm_h[c][kk], wv, acc[kk]);
    }
    const int p = blockIdx.y >> 2;
    const int ub = (blockIdx.y & 3) * 8;
    float sc = (p < 4) ? 0.015625f : 0.022097086912079608f;
    #pragma unroll
    for (int kk = 0; kk < 16; kk++)
        sm_buf[kk][t] = __float2half_rn(acc[kk] * sc);
    __syncthreads();

    // coalesced writeout: work item = (kk, w); gather 8 u-contiguous halfs -> 16B store
    for (int idx = t; idx < 16 * 32; idx += 256) {
        const int kk = idx >> 5, w = idx & 31;
        unsigned short h[8];
        #pragma unroll
        for (int ul = 0; ul < 8; ul++)
            h[ul] = __half_as_ushort(sm_buf[kk][ul * 32 + w]);
        uint4 v = *reinterpret_cast<uint4*>(h);
        const int row = kbase + kk;
        if (p < 4) {
            int n = (p >> 1) * 32 + w;
            int kb0 = (p & 1) * 32 + ub;
            if (row <= 62)
                *reinterpret_cast<uint4*>(&g_Bsg[(size_t)row * BSG_CELL + n * ST_SG + kb0]) = v;
            if (row >= 1)
                *reinterpret_cast<uint4*>(&g_Bsg[(size_t)(row - 1) * BSG_CELL + n * ST_SG + 64 + kb0]) = v;
        } else {
            int kb0 = (p - 4) * 32 + ub;
            if (row <= 62)
                *reinterpret_cast<uint4*>(&g_Bv[(size_t)row * BV_CELL + w * ST_V + kb0]) = v;
            if (row >= 1)
                *reinterpret_cast<uint4*>(&g_Bv[(size_t)(row - 1) * BV_CELL + w * ST_V + 96 + kb0]) = v;
        }
    }

    // ---- last-block scan (pad-16) + tile map + resets ----
    __threadfence();
    __syncthreads();
    if (t == 0) {
        int total = gridDim.x * gridDim.y;
        sm_last = (atomicAdd(&g_buildDone, 1) + 1 == total) ? 1 : 0;
    }
    __syncthreads();
    if (sm_last && t < 32) {
        int c0 = 2 * t, c1 = 2 * t + 1;
        int n0 = (c0 < NCELLS) ? g_binCount[c0] : 0;
        int n1 = (c1 < NCELLS) ? g_binCount[c1] : 0;
        int p0 = (n0 + 15) & ~15, p1 = (n1 + 15) & ~15;
        int s = p0 + p1;
        int x = s;
        #pragma unroll
        for (int o = 1; o < 32; o <<= 1) {
            int y = __shfl_up_sync(0xffffffffu, x, o);
            if (t >= o) x += y;
        }
        int base0 = x - s;
        int base1 = base0 + p0;
        g_binCursor[c0] = base0;
        g_binCursor[c1] = base1;
        for (int i = n0; i < p0; i++) g_perm[base0 + i] = -1;
        for (int i = n1; i < p1; i++) g_perm[base1 + i] = -1;
        for (int i = 0; i < (p0 >> 4); i++) g_tileCell[(base0 >> 4) + i] = c0;
        for (int i = 0; i < (p1 >> 4); i++) g_tileCell[(base1 >> 4) + i] = c1;
        int tot = __shfl_sync(0xffffffffu, x, 31);
        for (int i = (tot >> 4) + t; i < NTILES; i += 32) g_tileCell[i] = -1;
        g_binCount[c0] = 0;
        g_binCount[c1] = 0;
        if (t == 0) g_buildDone = 0;   // reset for graph replay
    }
}

// ---------------- kernel 2: two-level scatter + nodeacc zeroing ----------------
__global__ void k_scatterzero(const float* __restrict__ len, int E, int accTotal) {
    __shared__ int sCnt[64];
    __shared__ int sBase[64];
    const int t = threadIdx.x;
    const int gid = blockIdx.x * 256 + t;

    if (t < 64) sCnt[t] = 0;

    for (int i = gid; i < accTotal; i += gridDim.x * 256) g_nodeacc[i] = 0.0f;
    __syncthreads();

    int e = -1, bin = 0, rank = 0;
    if (gid < E) {
        e = gid;
        bin = cell_of(len[e]);
        rank = atomicAdd(&sCnt[bin], 1);
    }
    __syncthreads();
    if (t < 64) sBase[t] = (sCnt[t] > 0) ? atomicAdd(&g_binCursor[t], sCnt[t]) : 0;
    __syncthreads();
    if (e >= 0) g_perm[sBase[bin] + rank] = e;
}

// ---------------- kernel 3: tensor-core edge kernel ----------------
// CTA = 16 same-cell edges. 20 independent work items over 8 warps,
// ldmatrix fragment loads, red.global.add.v2.f32 epilogue.
#define OFF_AV  2176
#define OFF_BSG 11776
#define OFF_BV  20480
#define SMEM_HALFS 26880
#define SMEM_BYTES (SMEM_HALFS * 2 + 128)

__global__ __launch_bounds__(256, 4) void k_edge_mma(
        const float* __restrict__ x, const float* __restrict__ attr,
        const float* __restrict__ len, const int* __restrict__ src,
        const int* __restrict__ dst) {
    extern __shared__ __align__(16) __half smh[];
    __half* sAsg = smh;
    __half* sAv  = smh + OFF_AV;
    __half* sBsg = smh + OFF_BSG;
    __half* sBv  = smh + OFF_BV;
    int* sEdge = (int*)(smh + SMEM_HALFS);
    int* sDst  = sEdge + 16;

    const int tile = blockIdx.x;
    const int cell = g_tileCell[tile];
    if (cell < 0) return;
    const int t = threadIdx.x;
    const int lane = t & 31, warp = t >> 5;

    // ---- stage B (coalesced) ----
    {
        const uint4* gb = (const uint4*)(g_Bsg + (size_t)cell * BSG_CELL);
        uint4* sb = (uint4*)sBsg;
        for (int i = t; i < BSG_CELL / 8; i += 256) sb[i] = gb[i];
        const uint4* gv = (const uint4*)(g_Bv + (size_t)cell * BV_CELL);
        uint4* sv = (uint4*)sBv;
        for (int i = t; i < BV_CELL / 8; i += 256) sv[i] = gv[i];
    }

    // ---- feature phase: thread t -> edge e = t>>4, u in {t&15, (t&15)+16} ----
    {
        const int e = t >> 4, u0 = t & 15;
        int eg = g_perm[tile * 16 + e];
        float f = 0.0f;
        float y0 = 0, y10 = 0, y11 = 0, y12 = 0;
        float M00 = 0, M01 = 0, M02 = 0, M10 = 0, M11 = 0, M12 = 0, M20 = 0, M21 = 0, M22 = 0;
        const float* xr = x;   // dummy
        if (eg >= 0) {
            float L = len[eg];
            float tp = L * ((float)(KNOTS - 1) / 5.0f) - (float)cell;
            f = fminf(fmaxf(tp, 0.0f), 1.0f);
            const float* ar = attr + eg * 9;
            y0 = ar[0]; y10 = ar[1]; y11 = ar[2]; y12 = ar[3];
            float y20 = ar[4], y21 = ar[5], y22 = ar[6], y23 = ar[7], y24 = ar[8];
            const float cA = 0.31622776601683794f;
            const float cB = 0.18257418583505536f;
            const float cC = 0.36514837167011072f;
            M00 = -cB * y22 + cA * y24;
            M01 =  cA * y20;  M02 = cA * y23;
            M10 =  cA * y20;  M11 = -cB * y22 - cA * y24;  M12 = cA * y21;
            M20 =  cA * y23;  M21 = cA * y21;              M22 = cC * y22;
            xr = x + (size_t)src[eg] * 128;
        }
        float g1 = 1.0f - f;
        if (u0 == 0) {
            sEdge[e] = eg;
            int dn = (eg >= 0) ? dst[eg] : 0;
            sDst[e] = dn;
            if (eg >= 0) atomicAdd(g_nodeacc + (size_t)dn * NASTRIDE + 160, 1.0f);
        }
        const float IS3 = 0.5773502691896258f;
        #pragma unroll
        for (int half_ = 0; half_ < 2; half_++) {
            int u = u0 + half_ * 16;
            float F[11];
            #pragma unroll
            for (int k = 0; k < 11; k++) F[k] = 0.0f;
            if (eg >= 0) {
                float sj = xr[u];
                float v0 = xr[32 + 3 * u], v1 = xr[33 + 3 * u], v2 = xr[34 + 3 * u];
                F[0] = sj * y0;
                F[1] = (v0 * y10 + v1 * y11 + v2 * y12) * IS3;
                float sy = sj * IS3;
                F[2] = sy * y10; F[3] = sy * y11; F[4] = sy * y12;
                float yv = y0 * IS3;
                F[5] = v0 * yv; F[6] = v1 * yv; F[7] = v2 * yv;
                F[8]  = v0 * M00 + v1 * M10 + v2 * M20;
                F[9]  = v0 * M01 + v1 * M11 + v2 * M21;
                F[10] = v0 * M02 + v1 * M12 + v2 * M22;
            }
            __half* asg = sAsg + e * ST_SG;
            asg[u]      = __float2half_rn(F[0] * g1);
            asg[32 + u] = __float2half_rn(F[1] * g1);
            asg[64 + u] = __float2half_rn(F[0] * f);
            asg[96 + u] = __float2half_rn(F[1] * f);
            #pragma unroll
            for (int kc = 0; kc < 3; kc++) {
                __half* av = sAv + (kc * 16 + e) * ST_V;
                av[u]        = __float2half_rn(F[2 + kc] * g1);   // t01 -> path4
                av[32 + u]   = __float2half_rn(F[5 + kc] * g1);   // t10 -> path5
                av[64 + u]   = __float2half_rn(F[8 + kc] * g1);   // t12 -> path6
                av[96 + u]   = __float2half_rn(F[2 + kc] * f);
                av[128 + u]  = __float2half_rn(F[5 + kc] * f);
                av[160 + u]  = __float2half_rn(F[8 + kc] * f);
            }
        }
    }
    __syncthreads();

    // ---- MMA phase: 20 work items (8 SG n-tiles, 12 V (kcomp,n)-tiles) over 8 warps ----
    const int l15 = lane & 15;
    const int aoff = (lane >> 4) * 8;          // A fragment col-half select
    const int boff = ((l15 >> 3) & 1) * 8;     // B fragment col-half select
    const int bn   = l15 & 7;                  // B fragment row-in-tile

    for (int item = warp; item < 20; item += 8) {
        float c[4] = {0.f, 0.f, 0.f, 0.f};
        const __half *A, *B;
        int K, stA, nb;
        int isV = (item >= 8);
        int kcomp = 0;
        if (!isV) {
            A = sAsg; B = sBsg; K = 8; stA = ST_SG; nb = item * 8;
        } else {
            int idx = item - 8;
            kcomp = idx >> 2;
            int nt = idx & 3;
            A = sAv + kcomp * 16 * ST_V; B = sBv; K = 12; stA = ST_V; nb = nt * 8;
        }
        const int stB = stA;
        const unsigned aBase = smaddr(A + l15 * stA + aoff);
        const unsigned bBase = smaddr(B + (nb + bn) * stB + boff);
        for (int ks = 0; ks < K; ks++) {
            int kb2 = ks * 32;   // ks*16 halfs = ks*32 bytes
            unsigned a0, a1, a2, a3, b0, b1;
            ldsm4(a0, a1, a2, a3, aBase + kb2);
            ldsm2(b0, b1, bBase + kb2);
            mma16816(c, a0, a1, a2, a3, b0, b1);
        }
        // epilogue: rows r0, r0+8 = edges; cols cp, cp+1 contiguous -> red2
        const int r0 = lane >> 2, cp = (lane & 3) * 2;
        int ed0 = sEdge[r0], ed1 = sEdge[r0 + 8];
        int col = (!isV) ? (item * 8 + cp) : (64 + kcomp * 32 + nb + cp);
        if (ed0 >= 0) red2(g_nodeacc + (size_t)sDst[r0] * NASTRIDE + col, c[0], c[1]);
        if (ed1 >= 0) red2(g_nodeacc + (size_t)sDst[r0 + 8] * NASTRIDE + col, c[2], c[3]);
    }
}

// ---------------- kernel 4: mean, gating, self-connection, norms ----------------
// 16 nodes per CTA (512 threads); Wss/Wsv staged in smem once per CTA.
// nodeacc layout: [0:32) S, [32:64) G, [64+kcomp*32 + w] V, [160] count; stride 162.
__global__ __launch_bounds__(512) void k_node(
        const float* __restrict__ x, const float* __restrict__ Wss,
        const float* __restrict__ Wsv, float* __restrict__ out, int N) {
    __shared__ float sWss[1024];
    __shared__ float sWsv[1024];
    __shared__ float sx[16][128];
    const int t = threadIdx.x;
    const int warp = t >> 5, lane = t & 31;
    int n = blockIdx.x * 16 + warp;

    // stage weights (coalesced, 2 iters each)
    for (int i = t; i < 1024; i += 512) {
        sWss[i] = Wss[i];
        sWsv[i] = Wsv[i];
    }

    // batch all global loads before sync: x row + nodeacc row
    float4 xv = make_float4(0.f, 0.f, 0.f, 0.f);
    float ms = 0.f, mg = 0.f, mv0 = 0.f, mv1 = 0.f, mv2 = 0.f, cnt = 1.f;
    if (n < N) {
        xv = reinterpret_cast<const float4*>(x + (size_t)n * 128)[lane];
        const float* na = g_nodeacc + (size_t)n * NASTRIDE;
        ms  = na[lane];
        mg  = na[32 + lane];
        mv0 = na[64 + lane];
        mv1 = na[96 + lane];
        mv2 = na[128 + lane];
        cnt = na[160];
    }
    reinterpret_cast<float4*>(&sx[warp][0])[lane] = xv;
    __syncthreads();
    if (n >= N) return;

    float inv = 1.0f / fmaxf(cnt, 1.0f);
    ms *= inv; mg *= inv; mv0 *= inv; mv1 *= inv; mv2 *= inv;

    float gs   = ms / (1.0f + expf(-ms));
    float gate = 1.0f / (1.0f + expf(-mg));
    float gv0 = mv0 * gate, gv1 = mv1 * gate, gv2 = mv2 * gate;

    float ds = 0.f, dv0 = 0.f, dv1 = 0.f, dv2 = 0.f;
    #pragma unroll 8
    for (int u = 0; u < 32; u++) {
        float su  = sx[warp][u];
        float vu0 = sx[warp][32 + 3 * u], vu1 = sx[warp][33 + 3 * u], vu2 = sx[warp][34 + 3 * u];
        float a = sWss[u * 32 + lane];
        float b = sWsv[u * 32 + lane];
        ds  = fmaf(su,  a, ds);
        dv0 = fmaf(vu0, b, dv0);
        dv1 = fmaf(vu1, b, dv1);
        dv2 = fmaf(vu2, b, dv2);
    }
    const float ism = 0.17677669529663687f;   // 1/sqrt(32)
    float hs  = gs  + ds  * ism;
    float hv0 = gv0 + dv0 * ism;
    float hv1 = gv1 + dv1 * ism;
    float hv2 = gv2 + dv2 * ism;

    out[(size_t)n * 64 + lane]      = sqrtf(hs * hs + 1e-12f);
    out[(size_t)n * 64 + 32 + lane] = sqrtf(hv0 * hv0 + hv1 * hv1 + hv2 * hv2 + 1e-12f);
}

// ---------------- launch ----------------
extern "C" void kernel_launch(void* const* d_in, const int* in_sizes, int n_in,
                              void* d_out, int out_size) {
    const float* x    = (const float*)d_in[0];
    const float* attr = (const float*)d_in[1];
    const float* len  = (const float*)d_in[2];
    const int*   src  = (const int*)d_in[3];
    const int*   dst  = (const int*)d_in[4];
    const float* Wfc1 = (const float*)d_in[5];
    const float* Wfc2 = (const float*)d_in[6];
    const float* Wss  = (const float*)d_in[7];
    const float* Wsv  = (const float*)d_in[8];
    float* out = (float*)d_out;

    int N = in_sizes[0] / 128;
    int E = in_sizes[2];

    cudaFuncSetAttribute(k_edge_mma, cudaFuncAttributeMaxDynamicSharedMemorySize, SMEM_BYTES);

    dim3 bgrid(KNOTS / 16, 28);
    k_build<<<bgrid, 256>>>(Wfc1, Wfc2, len, E);                 // #1 (B + hist + scan)
    k_scatterzero<<<(E + 255) / 256, 256>>>(len, E, N * NASTRIDE);  // #2 (scatter + zero)
    k_edge_mma<<<NTILES, 256, SMEM_BYTES>>>(x, attr, len, src, dst);  // #3
    k_node<<<(N + 15) / 16, 512>>>(x, Wss, Wsv, out, N);         // #4
}

// round 16
// speedup vs baseline: 1.2044x; 1.0224x over previous
#include <cuda_runtime.h>
#include <cuda_fp16.h>
#include <math.h>

#define KNOTS 64
#define WCOLS 7168          // 7 paths * 32 u * 32 w
#define MAXN  4096
#define MAXE  32768
#define NCELLS 63           // cell_of in [0,62]
#define PERM_SZ (MAXE + 16 * 64)   // per-cell pad to mult of 16
#define NTILES  (PERM_SZ / 16)     // 2112
#define NASTRIDE 162        // even stride -> 8B-aligned red.v2 targets
#define TILES_PER_CTA 4
#define EDGE_GRID ((NTILES + TILES_PER_CTA - 1) / TILES_PER_CTA)   // 528

// B layouts (halfs), rows padded for conflict-free ldmatrix
#define ST_SG 136           // K=128 + 8 pad
#define ST_V  200           // K=192 + 8 pad
#define BSG_CELL (64 * ST_SG)   // 8704 halfs
#define BV_CELL  (32 * ST_V)    // 6400 halfs

// ---------------- scratch (device globals; no allocation allowed) ----------------
__device__ __align__(16) __half g_Bsg[64 * BSG_CELL];   // [cell][n=64][k=128 pad 136]
__device__ __align__(16) __half g_Bv [64 * BV_CELL];    // [cell][n=32][k=192 pad 200]
__device__ float g_nodeacc[MAXN * NASTRIDE];
__device__ int   g_binCount[64];
__device__ int   g_binCursor[64];
__device__ int   g_perm[PERM_SZ];
__device__ int   g_tileCell[NTILES];
__device__ int   g_buildDone;     // zero-init; self-resetting

__device__ __forceinline__ int cell_of(float L) {
    float t = L * ((float)(KNOTS - 1) / 5.0f);
    int i = (int)floorf(t);
    if (i < 0) i = 0;
    if (i > KNOTS - 2) i = KNOTS - 2;
    return i;
}

__device__ __forceinline__ unsigned smaddr(const void* p) {
    return (unsigned)__cvta_generic_to_shared(p);
}
__device__ __forceinline__ void ldsm4(unsigned& a0, unsigned& a1, unsigned& a2, unsigned& a3,
                                      unsigned addr) {
    asm volatile("ldmatrix.sync.aligned.m8n8.x4.shared.b16 {%0,%1,%2,%3}, [%4];"
                 : "=r"(a0), "=r"(a1), "=r"(a2), "=r"(a3) : "r"(addr));
}
__device__ __forceinline__ void ldsm2(unsigned& b0, unsigned& b1, unsigned addr) {
    asm volatile("ldmatrix.sync.aligned.m8n8.x2.shared.b16 {%0,%1}, [%2];"
                 : "=r"(b0), "=r"(b1) : "r"(addr));
}
__device__ __forceinline__ void mma16816(float* c, unsigned a0, unsigned a1, unsigned a2,
                                         unsigned a3, unsigned b0, unsigned b1) {
    asm volatile(
        "mma.sync.aligned.m16n8k16.row.col.f32.f16.f16.f32 "
        "{%0,%1,%2,%3}, {%4,%5,%6,%7}, {%8,%9}, {%0,%1,%2,%3};\n"
        : "+f"(c[0]), "+f"(c[1]), "+f"(c[2]), "+f"(c[3])
        : "r"(a0), "r"(a1), "r"(a2), "r"(a3), "r"(b0), "r"(b1));
}
__device__ __forceinline__ void red2(float* p, float a, float b) {
    asm volatile("red.global.add.v2.f32 [%0], {%1, %2};" :: "l"(p), "f"(a), "f"(b) : "memory");
}

// ---------------- kernel 1: build per-cell B matrices + histogram + (last block) scan ----
// Grid (4, 28), block 256: 16 knot-rows x 256 cols each. p = by>>2 const per block,
// u in [ub, ub+8) with ub = (by&3)*8, w = 0..31. Coalesced 16B table stores.
__global__ void k_build(const float* __restrict__ Wfc1, const float* __restrict__ Wfc2,
                        const float* __restrict__ len, int E) {
    __shared__ float sm_h[64][17];
    __shared__ int   sm_hist[64];
    __shared__ __half sm_buf[16][256];   // [kk][u_local*32+w]
    __shared__ int   sm_last;
    const int t = threadIdx.x;
    const int kbase = blockIdx.x * 16;
    const int col = blockIdx.y * 256 + t;

    if (t < 64) sm_hist[t] = 0;
    __syncthreads();

    {
        int gid = (blockIdx.y * gridDim.x + blockIdx.x) * 256 + t;
        int stride = gridDim.x * gridDim.y * 256;
        for (int e = gid; e < E; e += stride)
            atomicAdd(&sm_hist[cell_of(len[e])], 1);
    }

    for (int idx = t; idx < 16 * 64; idx += 256) {
        int kk = idx >> 6, c = idx & 63;
        float r = (float)(kbase + kk) * (5.0f / (float)(KNOTS - 1));
        float pre = 0.0f;
        #pragma unroll
        for (int j = 0; j < 8; j++) {
            float d = r - (float)j * (5.0f / 7.0f);
            float rad = expf(-d * d * 0.98f);
            pre += rad * Wfc1[j * 64 + c];
        }
        pre *= 0.35355339059327373f;                 // 1/sqrt(8)
        sm_h[c][kk] = pre / (1.0f + expf(-pre));     // silu
    }
    __syncthreads();

    if (t < 64 && sm_hist[t] > 0) atomicAdd(&g_binCount[t], sm_hist[t]);

    float acc[16];
    #pragma unroll
    for (int kk = 0; kk < 16; kk++) acc[kk] = 0.0f;
    #pragma unroll 4
    for (int c = 0; c < 64; c++) {
        float wv = __ldg(&Wfc2[c * WCOLS + col]);
        #pragma unroll
        for (int kk = 0; kk < 16; kk++) acc[kk] = fmaf(sm_h[c][kk], wv, acc[kk]);
    }
    const int p = blockIdx.y >> 2;
    const int ub = (blockIdx.y & 3) * 8;
    float sc = (p < 4) ? 0.015625f : 0.022097086912079608f;
    #pragma unroll
    for (int kk = 0; kk < 16; kk++)
        sm_buf[kk][t] = __float2half_rn(acc[kk] * sc);
    __syncthreads();

    // coalesced writeout: work item = (kk, w); gather 8 u-contiguous halfs -> 16B store
    for (int idx = t; idx < 16 * 32; idx += 256) {
        const int kk = idx >> 5, w = idx & 31;
        unsigned short h[8];
        #pragma unroll
        for (int ul = 0; ul < 8; ul++)
            h[ul] = __half_as_ushort(sm_buf[kk][ul * 32 + w]);
        uint4 v = *reinterpret_cast<uint4*>(h);
        const int row = kbase + kk;
        if (p < 4) {
            int n = (p >> 1) * 32 + w;
            int kb0 = (p & 1) * 32 + ub;
            if (row <= 62)
                *reinterpret_cast<uint4*>(&g_Bsg[(size_t)row * BSG_CELL + n * ST_SG + kb0]) = v;
            if (row >= 1)
                *reinterpret_cast<uint4*>(&g_Bsg[(size_t)(row - 1) * BSG_CELL + n * ST_SG + 64 + kb0]) = v;
        } else {
            int kb0 = (p - 4) * 32 + ub;
            if (row <= 62)
                *reinterpret_cast<uint4*>(&g_Bv[(size_t)row * BV_CELL + w * ST_V + kb0]) = v;
            if (row >= 1)
                *reinterpret_cast<uint4*>(&g_Bv[(size_t)(row - 1) * BV_CELL + w * ST_V + 96 + kb0]) = v;
        }
    }

    // ---- last-block scan (pad-16) + tile map + resets ----
    __threadfence();
    __syncthreads();
    if (t == 0) {
        int total = gridDim.x * gridDim.y;
        sm_last = (atomicAdd(&g_buildDone, 1) + 1 == total) ? 1 : 0;
    }
    __syncthreads();
    if (sm_last && t < 32) {
        int c0 = 2 * t, c1 = 2 * t + 1;
        int n0 = (c0 < NCELLS) ? g_binCount[c0] : 0;
        int n1 = (c1 < NCELLS) ? g_binCount[c1] : 0;
        int p0 = (n0 + 15) & ~15, p1 = (n1 + 15) & ~15;
        int s = p0 + p1;
        int x = s;
        #pragma unroll
        for (int o = 1; o < 32; o <<= 1) {
            int y = __shfl_up_sync(0xffffffffu, x, o);
            if (t >= o) x += y;
        }
        int base0 = x - s;
        int base1 = base0 + p0;
        g_binCursor[c0] = base0;
        g_binCursor[c1] = base1;
        for (int i = n0; i < p0; i++) g_perm[base0 + i] = -1;
        for (int i = n1; i < p1; i++) g_perm[base1 + i] = -1;
        for (int i = 0; i < (p0 >> 4); i++) g_tileCell[(base0 >> 4) + i] = c0;
        for (int i = 0; i < (p1 >> 4); i++) g_tileCell[(base1 >> 4) + i] = c1;
        int tot = __shfl_sync(0xffffffffu, x, 31);
        for (int i = (tot >> 4) + t; i < NTILES; i += 32) g_tileCell[i] = -1;
        g_binCount[c0] = 0;
        g_binCount[c1] = 0;
        if (t == 0) g_buildDone = 0;   // reset for graph replay
    }
}

// ---------------- kernel 2: two-level scatter + nodeacc zeroing ----------------
__global__ void k_scatterzero(const float* __restrict__ len, int E, int accTotal) {
    __shared__ int sCnt[64];
    __shared__ int sBase[64];
    const int t = threadIdx.x;
    const int gid = blockIdx.x * 256 + t;

    if (t < 64) sCnt[t] = 0;

    for (int i = gid; i < accTotal; i += gridDim.x * 256) g_nodeacc[i] = 0.0f;
    __syncthreads();

    int e = -1, bin = 0, rank = 0;
    if (gid < E) {
        e = gid;
        bin = cell_of(len[e]);
        rank = atomicAdd(&sCnt[bin], 1);
    }
    __syncthreads();
    if (t < 64) sBase[t] = (sCnt[t] > 0) ? atomicAdd(&g_binCursor[t], sCnt[t]) : 0;
    __syncthreads();
    if (e >= 0) g_perm[sBase[bin] + rank] = e;
}

// ---------------- kernel 3: tensor-core edge kernel (persistent 4-tile chunks) ------
// CTA processes 4 consecutive cell-sorted tiles, re-staging B only on cell change.
// Per tile: sync -> [restage] -> features -> sync -> MMA (20 items / 8 warps).
#define OFF_AV  2176
#define OFF_BSG 11776
#define OFF_BV  20480
#define SMEM_HALFS 26880
#define SMEM_BYTES (SMEM_HALFS * 2 + 128)

__global__ __launch_bounds__(256, 4) void k_edge_mma(
        const float* __restrict__ x, const float* __restrict__ attr,
        const float* __restrict__ len, const int* __restrict__ src,
        const int* __restrict__ dst) {
    extern __shared__ __align__(16) __half smh[];
    __half* sAsg = smh;
    __half* sAv  = smh + OFF_AV;
    __half* sBsg = smh + OFF_BSG;
    __half* sBv  = smh + OFF_BV;
    int* sEdge = (int*)(smh + SMEM_HALFS);
    int* sDst  = sEdge + 16;

    const int t = threadIdx.x;
    const int lane = t & 31, warp = t >> 5;
    const int l15 = lane & 15;
    const int aoff = (lane >> 4) * 8;          // A fragment col-half select
    const int boff = ((l15 >> 3) & 1) * 8;     // B fragment col-half select
    const int bn   = l15 & 7;                  // B fragment row-in-tile
    const float IS3 = 0.5773502691896258f;
    const float cA = 0.31622776601683794f;
    const float cB = 0.18257418583505536f;
    const float cC = 0.36514837167011072f;

    const int tile0 = blockIdx.x * TILES_PER_CTA;
    int curCell = -1;

    for (int tile = tile0; tile < tile0 + TILES_PER_CTA && tile < NTILES; tile++) {
        const int cell = g_tileCell[tile];
        if (cell < 0) break;                   // trailing empty tiles

        if (tile != tile0) __syncthreads();    // MMA(i-1) reads done before any smem writes

        // ---- (re)stage B only on cell change ----
        if (cell != curCell) {
            const uint4* gb = (const uint4*)(g_Bsg + (size_t)cell * BSG_CELL);
            uint4* sb = (uint4*)sBsg;
            for (int i = t; i < BSG_CELL / 8; i += 256) sb[i] = gb[i];
            const uint4* gv = (const uint4*)(g_Bv + (size_t)cell * BV_CELL);
            uint4* sv = (uint4*)sBv;
            for (int i = t; i < BV_CELL / 8; i += 256) sv[i] = gv[i];
            curCell = cell;
        }

        // ---- feature phase: thread t -> edge e = t>>4, u in {t&15, (t&15)+16} ----
        {
            const int e = t >> 4, u0 = t & 15;
            int eg = g_perm[tile * 16 + e];
            float f = 0.0f;
            float y0 = 0, y10 = 0, y11 = 0, y12 = 0;
            float M00 = 0, M01 = 0, M02 = 0, M10 = 0, M11 = 0, M12 = 0, M20 = 0, M21 = 0, M22 = 0;
            const float* xr = x;   // dummy
            if (eg >= 0) {
                float L = len[eg];
                float tp = L * ((float)(KNOTS - 1) / 5.0f) - (float)cell;
                f = fminf(fmaxf(tp, 0.0f), 1.0f);
                const float* ar = attr + eg * 9;
                y0 = ar[0]; y10 = ar[1]; y11 = ar[2]; y12 = ar[3];
                float y20 = ar[4], y21 = ar[5], y22 = ar[6], y23 = ar[7], y24 = ar[8];
                M00 = -cB * y22 + cA * y24;
                M01 =  cA * y20;  M02 = cA * y23;
                M10 =  cA * y20;  M11 = -cB * y22 - cA * y24;  M12 = cA * y21;
                M20 =  cA * y23;  M21 = cA * y21;              M22 = cC * y22;
                xr = x + (size_t)src[eg] * 128;
            }
            float g1 = 1.0f - f;
            if (u0 == 0) {
                sEdge[e] = eg;
                int dn = (eg >= 0) ? dst[eg] : 0;
                sDst[e] = dn;
                if (eg >= 0) atomicAdd(g_nodeacc + (size_t)dn * NASTRIDE + 160, 1.0f);
            }
            #pragma unroll
            for (int half_ = 0; half_ < 2; half_++) {
                int u = u0 + half_ * 16;
                float F[11];
                #pragma unroll
                for (int k = 0; k < 11; k++) F[k] = 0.0f;
                if (eg >= 0) {
                    float sj = xr[u];
                    float v0 = xr[32 + 3 * u], v1 = xr[33 + 3 * u], v2 = xr[34 + 3 * u];
                    F[0] = sj * y0;
                    F[1] = (v0 * y10 + v1 * y11 + v2 * y12) * IS3;
                    float sy = sj * IS3;
                    F[2] = sy * y10; F[3] = sy * y11; F[4] = sy * y12;
                    float yv = y0 * IS3;
                    F[5] = v0 * yv; F[6] = v1 * yv; F[7] = v2 * yv;
                    F[8]  = v0 * M00 + v1 * M10 + v2 * M20;
                    F[9]  = v0 * M01 + v1 * M11 + v2 * M21;
                    F[10] = v0 * M02 + v1 * M12 + v2 * M22;
                }
                __half* asg = sAsg + e * ST_SG;
                asg[u]      = __float2half_rn(F[0] * g1);
                asg[32 + u] = __float2half_rn(F[1] * g1);
                asg[64 + u] = __float2half_rn(F[0] * f);
                asg[96 + u] = __float2half_rn(F[1] * f);
                #pragma unroll
                for (int kc = 0; kc < 3; kc++) {
                    __half* av = sAv + (kc * 16 + e) * ST_V;
                    av[u]        = __float2half_rn(F[2 + kc] * g1);   // t01 -> path4
                    av[32 + u]   = __float2half_rn(F[5 + kc] * g1);   // t10 -> path5
                    av[64 + u]   = __float2half_rn(F[8 + kc] * g1);   // t12 -> path6
                    av[96 + u]   = __float2half_rn(F[2 + kc] * f);
                    av[128 + u]  = __float2half_rn(F[5 + kc] * f);
                    av[160 + u]  = __float2half_rn(F[8 + kc] * f);
                }
            }
        }
        __syncthreads();

        // ---- MMA phase: 20 work items (8 SG n-tiles, 12 V (kcomp,n)-tiles) ----
        for (int item = warp; item < 20; item += 8) {
            float c[4] = {0.f, 0.f, 0.f, 0.f};
            const __half *A, *B;
            int K, stA, nb;
            int isV = (item >= 8);
            int kcomp = 0;
            if (!isV) {
                A = sAsg; B = sBsg; K = 8; stA = ST_SG; nb = item * 8;
            } else {
                int idx = item - 8;
                kcomp = idx >> 2;
                int nt = idx & 3;
                A = sAv + kcomp * 16 * ST_V; B = sBv; K = 12; stA = ST_V; nb = nt * 8;
            }
            const int stB = stA;
            const unsigned aBase = smaddr(A + l15 * stA + aoff);
            const unsigned bBase = smaddr(B + (nb + bn) * stB + boff);
            for (int ks = 0; ks < K; ks++) {
                int kb2 = ks * 32;   // ks*16 halfs = ks*32 bytes
                unsigned a0, a1, a2, a3, b0, b1;
                ldsm4(a0, a1, a2, a3, aBase + kb2);
                ldsm2(b0, b1, bBase + kb2);
                mma16816(c, a0, a1, a2, a3, b0, b1);
            }
            // epilogue: rows r0, r0+8 = edges; cols cp, cp+1 contiguous -> red2
            const int r0 = lane >> 2, cp = (lane & 3) * 2;
            int ed0 = sEdge[r0], ed1 = sEdge[r0 + 8];
            int col = (!isV) ? (item * 8 + cp) : (64 + kcomp * 32 + nb + cp);
            if (ed0 >= 0) red2(g_nodeacc + (size_t)sDst[r0] * NASTRIDE + col, c[0], c[1]);
            if (ed1 >= 0) red2(g_nodeacc + (size_t)sDst[r0 + 8] * NASTRIDE + col, c[2], c[3]);
        }
    }
}

// ---------------- kernel 4: mean, gating, self-connection, norms ----------------
// 16 nodes per CTA (512 threads); Wss/Wsv staged in smem once per CTA.
// nodeacc layout: [0:32) S, [32:64) G, [64+kcomp*32 + w] V, [160] count; stride 162.
__global__ __launch_bounds__(512) void k_node(
        const float* __restrict__ x, const float* __restrict__ Wss,
        const float* __restrict__ Wsv, float* __restrict__ out, int N) {
    __shared__ float sWss[1024];
    __shared__ float sWsv[1024];
    __shared__ float sx[16][128];
    const int t = threadIdx.x;
    const int warp = t >> 5, lane = t & 31;
    int n = blockIdx.x * 16 + warp;

    // stage weights (coalesced, 2 iters each)
    for (int i = t; i < 1024; i += 512) {
        sWss[i] = Wss[i];
        sWsv[i] = Wsv[i];
    }

    // batch all global loads before sync: x row + nodeacc row
    float4 xv = make_float4(0.f, 0.f, 0.f, 0.f);
    float ms = 0.f, mg = 0.f, mv0 = 0.f, mv1 = 0.f, mv2 = 0.f, cnt = 1.f;
    if (n < N) {
        xv = reinterpret_cast<const float4*>(x + (size_t)n * 128)[lane];
        const float* na = g_nodeacc + (size_t)n * NASTRIDE;
        ms  = na[lane];
        mg  = na[32 + lane];
        mv0 = na[64 + lane];
        mv1 = na[96 + lane];
        mv2 = na[128 + lane];
        cnt = na[160];
    }
    reinterpret_cast<float4*>(&sx[warp][0])[lane] = xv;
    __syncthreads();
    if (n >= N) return;

    float inv = 1.0f / fmaxf(cnt, 1.0f);
    ms *= inv; mg *= inv; mv0 *= inv; mv1 *= inv; mv2 *= inv;

    float gs   = ms / (1.0f + expf(-ms));
    float gate = 1.0f / (1.0f + expf(-mg));
    float gv0 = mv0 * gate, gv1 = mv1 * gate, gv2 = mv2 * gate;

    float ds = 0.f, dv0 = 0.f, dv1 = 0.f, dv2 = 0.f;
    #pragma unroll 8
    for (int u = 0; u < 32; u++) {
        float su  = sx[warp][u];
        float vu0 = sx[warp][32 + 3 * u], vu1 = sx[warp][33 + 3 * u], vu2 = sx[warp][34 + 3 * u];
        float a = sWss[u * 32 + lane];
        float b = sWsv[u * 32 + lane];
        ds  = fmaf(su,  a, ds);
        dv0 = fmaf(vu0, b, dv0);
        dv1 = fmaf(vu1, b, dv1);
        dv2 = fmaf(vu2, b, dv2);
    }
    const float ism = 0.17677669529663687f;   // 1/sqrt(32)
    float hs  = gs  + ds  * ism;
    float hv0 = gv0 + dv0 * ism;
    float hv1 = gv1 + dv1 * ism;
    float hv2 = gv2 + dv2 * ism;

    out[(size_t)n * 64 + lane]      = sqrtf(hs * hs + 1e-12f);
    out[(size_t)n * 64 + 32 + lane] = sqrtf(hv0 * hv0 + hv1 * hv1 + hv2 * hv2 + 1e-12f);
}

// ---------------- launch ----------------
extern "C" void kernel_launch(void* const* d_in, const int* in_sizes, int n_in,
                              void* d_out, int out_size) {
    const float* x    = (const float*)d_in[0];
    const float* attr = (const float*)d_in[1];
    const float* len  = (const float*)d_in[2];
    const int*   src  = (const int*)d_in[3];
    const int*   dst  = (const int*)d_in[4];
    const float* Wfc1 = (const float*)d_in[5];
    const float* Wfc2 = (const float*)d_in[6];
    const float* Wss  = (const float*)d_in[7];
    const float* Wsv  = (const float*)d_in[8];
    float* out = (float*)d_out;

    int N = in_sizes[0] / 128;
    int E = in_sizes[2];

    cudaFuncSetAttribute(k_edge_mma, cudaFuncAttributeMaxDynamicSharedMemorySize, SMEM_BYTES);

    dim3 bgrid(KNOTS / 16, 28);
    k_build<<<bgrid, 256>>>(Wfc1, Wfc2, len, E);                 // #1 (B + hist + scan)
    k_scatterzero<<<(E + 255) / 256, 256>>>(len, E, N * NASTRIDE);  // #2 (scatter + zero)
    k_edge_mma<<<EDGE_GRID, 256, SMEM_BYTES>>>(x, attr, len, src, dst);  // #3 (persistent)
    k_node<<<(N + 15) / 16, 512>>>(x, Wss, Wsv, out, N);         // #4
}

// round 17
// speedup vs baseline: 1.2461x; 1.0347x over previous
#include <cuda_runtime.h>
#include <cuda_fp16.h>
#include <math.h>

#define KNOTS 64
#define WCOLS 7168          // 7 paths * 32 u * 32 w
#define MAXN  4096
#define MAXE  32768
#define NCELLS 63           // cell_of in [0,62]
#define PERM_SZ (MAXE + 16 * 64)   // per-cell pad to mult of 16
#define NTILES  (PERM_SZ / 16)     // 2112
#define NASTRIDE 162        // even stride -> 8B-aligned red.v2 targets
#define TILES_PER_CTA 4
#define EDGE_GRID ((NTILES + TILES_PER_CTA - 1) / TILES_PER_CTA)   // 528

// B layouts (halfs), rows padded for conflict-free ldmatrix
#define ST_SG 136           // K=128 + 8 pad
#define ST_V  200           // K=192 + 8 pad
#define BSG_CELL (64 * ST_SG)   // 8704 halfs
#define BV_CELL  (32 * ST_V)    // 6400 halfs

// ---------------- scratch (device globals; no allocation allowed) ----------------
__device__ __align__(16) __half g_Bsg[64 * BSG_CELL];   // [cell][n=64][k=128 pad 136]
__device__ __align__(16) __half g_Bv [64 * BV_CELL];    // [cell][n=32][k=192 pad 200]
__device__ float g_nodeacc[MAXN * NASTRIDE];
__device__ int   g_binCount[64];
__device__ int   g_binCursor[64];
__device__ int   g_perm[PERM_SZ];
__device__ int   g_tileCell[NTILES];
__device__ int   g_buildDone;     // zero-init; self-resetting

__device__ __forceinline__ int cell_of(float L) {
    float t = L * ((float)(KNOTS - 1) / 5.0f);
    int i = (int)floorf(t);
    if (i < 0) i = 0;
    if (i > KNOTS - 2) i = KNOTS - 2;
    return i;
}

__device__ __forceinline__ unsigned smaddr(const void* p) {
    return (unsigned)__cvta_generic_to_shared(p);
}
__device__ __forceinline__ void ldsm4(unsigned& a0, unsigned& a1, unsigned& a2, unsigned& a3,
                                      unsigned addr) {
    asm volatile("ldmatrix.sync.aligned.m8n8.x4.shared.b16 {%0,%1,%2,%3}, [%4];"
                 : "=r"(a0), "=r"(a1), "=r"(a2), "=r"(a3) : "r"(addr));
}
__device__ __forceinline__ void ldsm2(unsigned& b0, unsigned& b1, unsigned addr) {
    asm volatile("ldmatrix.sync.aligned.m8n8.x2.shared.b16 {%0,%1}, [%2];"
                 : "=r"(b0), "=r"(b1) : "r"(addr));
}
__device__ __forceinline__ void mma16816(float* c, unsigned a0, unsigned a1, unsigned a2,
                                         unsigned a3, unsigned b0, unsigned b1) {
    asm volatile(
        "mma.sync.aligned.m16n8k16.row.col.f32.f16.f16.f32 "
        "{%0,%1,%2,%3}, {%4,%5,%6,%7}, {%8,%9}, {%0,%1,%2,%3};\n"
        : "+f"(c[0]), "+f"(c[1]), "+f"(c[2]), "+f"(c[3])
        : "r"(a0), "r"(a1), "r"(a2), "r"(a3), "r"(b0), "r"(b1));
}
__device__ __forceinline__ void red2(float* p, float a, float b) {
    asm volatile("red.global.add.v2.f32 [%0], {%1, %2};" :: "l"(p), "f"(a), "f"(b) : "memory");
}

// ---------------- kernel 1: build per-cell B matrices + histogram + (last block) scan ----
__global__ void k_build(const float* __restrict__ Wfc1, const float* __restrict__ Wfc2,
                        const float* __restrict__ len, int E) {
    __shared__ float sm_h[64][17];
    __shared__ int   sm_hist[64];
    __shared__ __half sm_buf[16][256];   // [kk][u_local*32+w]
    __shared__ int   sm_last;
    const int t = threadIdx.x;
    const int kbase = blockIdx.x * 16;
    const int col = blockIdx.y * 256 + t;

    if (t < 64) sm_hist[t] = 0;
    __syncthreads();

    {
        int gid = (blockIdx.y * gridDim.x + blockIdx.x) * 256 + t;
        int stride = gridDim.x * gridDim.y * 256;
        for (int e = gid; e < E; e += stride)
            atomicAdd(&sm_hist[cell_of(len[e])], 1);
    }

    for (int idx = t; idx < 16 * 64; idx += 256) {
        int kk = idx >> 6, c = idx & 63;
        float r = (float)(kbase + kk) * (5.0f / (float)(KNOTS - 1));
        float pre = 0.0f;
        #pragma unroll
        for (int j = 0; j < 8; j++) {
            float d = r - (float)j * (5.0f / 7.0f);
            float rad = expf(-d * d * 0.98f);
            pre += rad * Wfc1[j * 64 + c];
        }
        pre *= 0.35355339059327373f;                 // 1/sqrt(8)
        sm_h[c][kk] = pre / (1.0f + expf(-pre));     // silu
    }
    __syncthreads();

    if (t < 64 && sm_hist[t] > 0) atomicAdd(&g_binCount[t], sm_hist[t]);

    float acc[16];
    #pragma unroll
    for (int kk = 0; kk < 16; kk++) acc[kk] = 0.0f;
    #pragma unroll 4
    for (int c = 0; c < 64; c++) {
        float wv = __ldg(&Wfc2[c * WCOLS + col]);
        #pragma unroll
        for (int kk = 0; kk < 16; kk++) acc[kk] = fmaf(sm_h[c][kk], wv, acc[kk]);
    }
    const int p = blockIdx.y >> 2;
    const int ub = (blockIdx.y & 3) * 8;
    float sc = (p < 4) ? 0.015625f : 0.022097086912079608f;
    #pragma unroll
    for (int kk = 0; kk < 16; kk++)
        sm_buf[kk][t] = __float2half_rn(acc[kk] * sc);
    __syncthreads();

    // coalesced writeout: work item = (kk, w); gather 8 u-contiguous halfs -> 16B store
    for (int idx = t; idx < 16 * 32; idx += 256) {
        const int kk = idx >> 5, w = idx & 31;
        unsigned short h[8];
        #pragma unroll
        for (int ul = 0; ul < 8; ul++)
            h[ul] = __half_as_ushort(sm_buf[kk][ul * 32 + w]);
        uint4 v = *reinterpret_cast<uint4*>(h);
        const int row = kbase + kk;
        if (p < 4) {
            int n = (p >> 1) * 32 + w;
            int kb0 = (p & 1) * 32 + ub;
            if (row <= 62)
                *reinterpret_cast<uint4*>(&g_Bsg[(size_t)row * BSG_CELL + n * ST_SG + kb0]) = v;
            if (row >= 1)
                *reinterpret_cast<uint4*>(&g_Bsg[(size_t)(row - 1) * BSG_CELL + n * ST_SG + 64 + kb0]) = v;
        } else {
            int kb0 = (p - 4) * 32 + ub;
            if (row <= 62)
                *reinterpret_cast<uint4*>(&g_Bv[(size_t)row * BV_CELL + w * ST_V + kb0]) = v;
            if (row >= 1)
                *reinterpret_cast<uint4*>(&g_Bv[(size_t)(row - 1) * BV_CELL + w * ST_V + 96 + kb0]) = v;
        }
    }

    // ---- last-block scan (pad-16) + tile map + resets ----
    __threadfence();
    __syncthreads();
    if (t == 0) {
        int total = gridDim.x * gridDim.y;
        sm_last = (atomicAdd(&g_buildDone, 1) + 1 == total) ? 1 : 0;
    }
    __syncthreads();
    if (sm_last && t < 32) {
        int c0 = 2 * t, c1 = 2 * t + 1;
        int n0 = (c0 < NCELLS) ? g_binCount[c0] : 0;
        int n1 = (c1 < NCELLS) ? g_binCount[c1] : 0;
        int p0 = (n0 + 15) & ~15, p1 = (n1 + 15) & ~15;
        int s = p0 + p1;
        int x = s;
        #pragma unroll
        for (int o = 1; o < 32; o <<= 1) {
            int y = __shfl_up_sync(0xffffffffu, x, o);
            if (t >= o) x += y;
        }
        int base0 = x - s;
        int base1 = base0 + p0;
        g_binCursor[c0] = base0;
        g_binCursor[c1] = base1;
        for (int i = n0; i < p0; i++) g_perm[base0 + i] = -1;
        for (int i = n1; i < p1; i++) g_perm[base1 + i] = -1;
        for (int i = 0; i < (p0 >> 4); i++) g_tileCell[(base0 >> 4) + i] = c0;
        for (int i = 0; i < (p1 >> 4); i++) g_tileCell[(base1 >> 4) + i] = c1;
        int tot = __shfl_sync(0xffffffffu, x, 31);
        for (int i = (tot >> 4) + t; i < NTILES; i += 32) g_tileCell[i] = -1;
        g_binCount[c0] = 0;
        g_binCount[c1] = 0;
        if (t == 0) g_buildDone = 0;   // reset for graph replay
    }
}

// ---------------- kernel 2: two-level scatter + nodeacc zeroing ----------------
__global__ void k_scatterzero(const float* __restrict__ len, int E, int accTotal) {
    __shared__ int sCnt[64];
    __shared__ int sBase[64];
    const int t = threadIdx.x;
    const int gid = blockIdx.x * 256 + t;

    if (t < 64) sCnt[t] = 0;

    for (int i = gid; i < accTotal; i += gridDim.x * 256) g_nodeacc[i] = 0.0f;
    __syncthreads();

    int e = -1, bin = 0, rank = 0;
    if (gid < E) {
        e = gid;
        bin = cell_of(len[e]);
        rank = atomicAdd(&sCnt[bin], 1);
    }
    __syncthreads();
    if (t < 64) sBase[t] = (sCnt[t] > 0) ? atomicAdd(&g_binCursor[t], sCnt[t]) : 0;
    __syncthreads();
    if (e >= 0) g_perm[sBase[bin] + rank] = e;
}

// ---------------- kernel 3: tensor-core edge kernel (persistent 4-tile chunks) ------
// Balanced MMA: warp w does SG n-tile w (8 MMAs) + V half-item w (6 ks x 3 kcomp = 18
// MMAs, shared B fragments, 3 independent accumulator chains). 26 MMAs per warp.
// Feature phase: thread handles adjacent u pair -> __half2 stores.
#define OFF_AV  2176
#define OFF_BSG 11776
#define OFF_BV  20480
#define SMEM_HALFS 26880
#define SMEM_BYTES (SMEM_HALFS * 2 + 128)

__global__ __launch_bounds__(256, 4) void k_edge_mma(
        const float* __restrict__ x, const float* __restrict__ attr,
        const float* __restrict__ len, const int* __restrict__ src,
        const int* __restrict__ dst) {
    extern __shared__ __align__(16) __half smh[];
    __half* sAsg = smh;
    __half* sAv  = smh + OFF_AV;
    __half* sBsg = smh + OFF_BSG;
    __half* sBv  = smh + OFF_BV;
    int* sEdge = (int*)(smh + SMEM_HALFS);
    int* sDst  = sEdge + 16;

    const int t = threadIdx.x;
    const int lane = t & 31, warp = t >> 5;
    const int l15 = lane & 15;
    const int aoff = (lane >> 4) * 8;          // A fragment col-half select
    const int boff = ((l15 >> 3) & 1) * 8;     // B fragment col-half select
    const int bn   = l15 & 7;                  // B fragment row-in-tile
    const float IS3 = 0.5773502691896258f;
    const float cA = 0.31622776601683794f;
    const float cB = 0.18257418583505536f;
    const float cC = 0.36514837167011072f;

    const int tile0 = blockIdx.x * TILES_PER_CTA;
    int curCell = -1;

    for (int tile = tile0; tile < tile0 + TILES_PER_CTA && tile < NTILES; tile++) {
        const int cell = g_tileCell[tile];
        if (cell < 0) break;                   // trailing empty tiles

        if (tile != tile0) __syncthreads();    // MMA(i-1) reads done before any smem writes

        // ---- (re)stage B only on cell change ----
        if (cell != curCell) {
            const uint4* gb = (const uint4*)(g_Bsg + (size_t)cell * BSG_CELL);
            uint4* sb = (uint4*)sBsg;
            for (int i = t; i < BSG_CELL / 8; i += 256) sb[i] = gb[i];
            const uint4* gv = (const uint4*)(g_Bv + (size_t)cell * BV_CELL);
            uint4* sv = (uint4*)sBv;
            for (int i = t; i < BV_CELL / 8; i += 256) sv[i] = gv[i];
            curCell = cell;
        }

        // ---- feature phase: thread t -> edge e = t>>4, u pair {2*(t&15), 2*(t&15)+1} ----
        {
            const int e = t >> 4, u0 = t & 15;
            int eg = g_perm[tile * 16 + e];
            float f = 0.0f;
            float y0 = 0, y10 = 0, y11 = 0, y12 = 0;
            float M00 = 0, M01 = 0, M02 = 0, M10 = 0, M11 = 0, M12 = 0, M20 = 0, M21 = 0, M22 = 0;
            const float* xr = x;   // dummy
            if (eg >= 0) {
                float L = len[eg];
                float tp = L * ((float)(KNOTS - 1) / 5.0f) - (float)cell;
                f = fminf(fmaxf(tp, 0.0f), 1.0f);
                const float* ar = attr + eg * 9;
                y0 = ar[0]; y10 = ar[1]; y11 = ar[2]; y12 = ar[3];
                float y20 = ar[4], y21 = ar[5], y22 = ar[6], y23 = ar[7], y24 = ar[8];
                M00 = -cB * y22 + cA * y24;
                M01 =  cA * y20;  M02 = cA * y23;
                M10 =  cA * y20;  M11 = -cB * y22 - cA * y24;  M12 = cA * y21;
                M20 =  cA * y23;  M21 = cA * y21;              M22 = cC * y22;
                xr = x + (size_t)src[eg] * 128;
            }
            float g1 = 1.0f - f;
            if (u0 == 0) {
                sEdge[e] = eg;
                int dn = (eg >= 0) ? dst[eg] : 0;
                sDst[e] = dn;
                if (eg >= 0) atomicAdd(g_nodeacc + (size_t)dn * NASTRIDE + 160, 1.0f);
            }
            float F2[11][2];
            #pragma unroll
            for (int k = 0; k < 11; k++) { F2[k][0] = 0.0f; F2[k][1] = 0.0f; }
            if (eg >= 0) {
                // vector loads: sj pair + 6 contiguous v floats
                float2 sj2 = *reinterpret_cast<const float2*>(xr + 2 * u0);
                const float2* vp = reinterpret_cast<const float2*>(xr + 32 + 6 * u0);
                float2 va = vp[0], vb = vp[1], vc = vp[2];
                #pragma unroll
                for (int half_ = 0; half_ < 2; half_++) {
                    float sj = half_ ? sj2.y : sj2.x;
                    float v0 = half_ ? vb.y : va.x;
                    float v1 = half_ ? vc.x : va.y;
                    float v2 = half_ ? vc.y : vb.x;
                    F2[0][half_] = sj * y0;
                    F2[1][half_] = (v0 * y10 + v1 * y11 + v2 * y12) * IS3;
                    float sy = sj * IS3;
                    F2[2][half_] = sy * y10; F2[3][half_] = sy * y11; F2[4][half_] = sy * y12;
                    float yv = y0 * IS3;
                    F2[5][half_] = v0 * yv; F2[6][half_] = v1 * yv; F2[7][half_] = v2 * yv;
                    F2[8][half_]  = v0 * M00 + v1 * M10 + v2 * M20;
                    F2[9][half_]  = v0 * M01 + v1 * M11 + v2 * M21;
                    F2[10][half_] = v0 * M02 + v1 * M12 + v2 * M22;
                }
            }
            const int up = 2 * u0;   // even
            __half* asg = sAsg + e * ST_SG;
            *reinterpret_cast<__half2*>(asg + up)      = __floats2half2_rn(F2[0][0] * g1, F2[0][1] * g1);
            *reinterpret_cast<__half2*>(asg + 32 + up) = __floats2half2_rn(F2[1][0] * g1, F2[1][1] * g1);
            *reinterpret_cast<__half2*>(asg + 64 + up) = __floats2half2_rn(F2[0][0] * f,  F2[0][1] * f);
            *reinterpret_cast<__half2*>(asg + 96 + up) = __floats2half2_rn(F2[1][0] * f,  F2[1][1] * f);
            #pragma unroll
            for (int kc = 0; kc < 3; kc++) {
                __half* av = sAv + (kc * 16 + e) * ST_V;
                *reinterpret_cast<__half2*>(av + up)        = __floats2half2_rn(F2[2 + kc][0] * g1, F2[2 + kc][1] * g1);
                *reinterpret_cast<__half2*>(av + 32 + up)   = __floats2half2_rn(F2[5 + kc][0] * g1, F2[5 + kc][1] * g1);
                *reinterpret_cast<__half2*>(av + 64 + up)   = __floats2half2_rn(F2[8 + kc][0] * g1, F2[8 + kc][1] * g1);
                *reinterpret_cast<__half2*>(av + 96 + up)   = __floats2half2_rn(F2[2 + kc][0] * f,  F2[2 + kc][1] * f);
                *reinterpret_cast<__half2*>(av + 128 + up)  = __floats2half2_rn(F2[5 + kc][0] * f,  F2[5 + kc][1] * f);
                *reinterpret_cast<__half2*>(av + 160 + up)  = __floats2half2_rn(F2[8 + kc][0] * f,  F2[8 + kc][1] * f);
            }
        }
        __syncthreads();

        const int r0 = lane >> 2, cp = (lane & 3) * 2;
        const int ed0 = sEdge[r0], ed1 = sEdge[r0 + 8];
        float* na0 = g_nodeacc + (size_t)sDst[r0] * NASTRIDE;
        float* na1 = g_nodeacc + (size_t)sDst[r0 + 8] * NASTRIDE;

        // ---- SG item: n-tile = warp, K=8 ----
        {
            float c[4] = {0.f, 0.f, 0.f, 0.f};
            const int nb = warp * 8;
            const unsigned aBase = smaddr(sAsg + l15 * ST_SG + aoff);
            const unsigned bBase = smaddr(sBsg + (nb + bn) * ST_SG + boff);
            #pragma unroll
            for (int ks = 0; ks < 8; ks++) {
                int kb2 = ks * 32;
                unsigned a0, a1, a2, a3, b0, b1;
                ldsm4(a0, a1, a2, a3, aBase + kb2);
                ldsm2(b0, b1, bBase + kb2);
                mma16816(c, a0, a1, a2, a3, b0, b1);
            }
            int col = nb + cp;
            if (ed0 >= 0) red2(na0 + col, c[0], c[1]);
            if (ed1 >= 0) red2(na1 + col, c[2], c[3]);
        }

        // ---- V half-item: nt = warp&3, ks-half = warp>>2; shared B, 3 acc chains ----
        {
            float c[3][4];
            #pragma unroll
            for (int kc = 0; kc < 3; kc++)
                #pragma unroll
                for (int q = 0; q < 4; q++) c[kc][q] = 0.0f;
            const int nt = warp & 3, ksh = warp >> 2;
            const int nb = nt * 8;
            const unsigned aB0 = smaddr(sAv + l15 * ST_V + aoff);
            const unsigned bBase = smaddr(sBv + (nb + bn) * ST_V + boff);
            const int AV_STEP = 16 * ST_V * 2;   // bytes per kcomp block
            #pragma unroll
            for (int ks6 = 0; ks6 < 6; ks6++) {
                int kb2 = (ksh * 6 + ks6) * 32;
                unsigned b0, b1;
                ldsm2(b0, b1, bBase + kb2);
                #pragma unroll
                for (int kc = 0; kc < 3; kc++) {
                    unsigned a0, a1, a2, a3;
                    ldsm4(a0, a1, a2, a3, aB0 + kc * AV_STEP + kb2);
                    mma16816(c[kc], a0, a1, a2, a3, b0, b1);
                }
            }
            #pragma unroll
            for (int kc = 0; kc < 3; kc++) {
                int col = 64 + kc * 32 + nb + cp;
                if (ed0 >= 0) red2(na0 + col, c[kc][0], c[kc][1]);
                if (ed1 >= 0) red2(na1 + col, c[kc][2], c[kc][3]);
            }
        }
    }
}

// ---------------- kernel 4: mean, gating, self-connection, norms ----------------
// 16 nodes per CTA (512 threads); Wss/Wsv staged in smem once per CTA.
// nodeacc layout: [0:32) S, [32:64) G, [64+kcomp*32 + w] V, [160] count; stride 162.
__global__ __launch_bounds__(512) void k_node(
        const float* __restrict__ x, const float* __restrict__ Wss,
        const float* __restrict__ Wsv, float* __restrict__ out, int N) {
    __shared__ float sWss[1024];
    __shared__ float sWsv[1024];
    __shared__ float sx[16][128];
    const int t = threadIdx.x;
    const int warp = t >> 5, lane = t & 31;
    int n = blockIdx.x * 16 + warp;

    // stage weights (coalesced, 2 iters each)
    for (int i = t; i < 1024; i += 512) {
        sWss[i] = Wss[i];
        sWsv[i] = Wsv[i];
    }

    // batch all global loads before sync: x row + nodeacc row
    float4 xv = make_float4(0.f, 0.f, 0.f, 0.f);
    float ms = 0.f, mg = 0.f, mv0 = 0.f, mv1 = 0.f, mv2 = 0.f, cnt = 1.f;
    if (n < N) {
        xv = reinterpret_cast<const float4*>(x + (size_t)n * 128)[lane];
        const float* na = g_nodeacc + (size_t)n * NASTRIDE;
        ms  = na[lane];
        mg  = na[32 + lane];
        mv0 = na[64 + lane];
        mv1 = na[96 + lane];
        mv2 = na[128 + lane];
        cnt = na[160];
    }
    reinterpret_cast<float4*>(&sx[warp][0])[lane] = xv;
    __syncthreads();
    if (n >= N) return;

    float inv = 1.0f / fmaxf(cnt, 1.0f);
    ms *= inv; mg *= inv; mv0 *= inv; mv1 *= inv; mv2 *= inv;

    float gs   = ms / (1.0f + expf(-ms));
    float gate = 1.0f / (1.0f + expf(-mg));
    float gv0 = mv0 * gate, gv1 = mv1 * gate, gv2 = mv2 * gate;

    float ds = 0.f, dv0 = 0.f, dv1 = 0.f, dv2 = 0.f;
    #pragma unroll 8
    for (int u = 0; u < 32; u++) {
        float su  = sx[warp][u];
        float vu0 = sx[warp][32 + 3 * u], vu1 = sx[warp][33 + 3 * u], vu2 = sx[warp][34 + 3 * u];
        float a = sWss[u * 32 + lane];
        float b = sWsv[u * 32 + lane];
        ds  = fmaf(su,  a, ds);
        dv0 = fmaf(vu0, b, dv0);
        dv1 = fmaf(vu1, b, dv1);
        dv2 = fmaf(vu2, b, dv2);
    }
    const float ism = 0.17677669529663687f;   // 1/sqrt(32)
    float hs  = gs  + ds  * ism;
    float hv0 = gv0 + dv0 * ism;
    float hv1 = gv1 + dv1 * ism;
    float hv2 = gv2 + dv2 * ism;

    out[(size_t)n * 64 + lane]      = sqrtf(hs * hs + 1e-12f);
    out[(size_t)n * 64 + 32 + lane] = sqrtf(hv0 * hv0 + hv1 * hv1 + hv2 * hv2 + 1e-12f);
}

// ---------------- launch ----------------
extern "C" void kernel_launch(void* const* d_in, const int* in_sizes, int n_in,
                              void* d_out, int out_size) {
    const float* x    = (const float*)d_in[0];
    const float* attr = (const float*)d_in[1];
    const float* len  = (const float*)d_in[2];
    const int*   src  = (const int*)d_in[3];
    const int*   dst  = (const int*)d_in[4];
    const float* Wfc1 = (const float*)d_in[5];
    const float* Wfc2 = (const float*)d_in[6];
    const float* Wss  = (const float*)d_in[7];
    const float* Wsv  = (const float*)d_in[8];
    float* out = (float*)d_out;

    int N = in_sizes[0] / 128;
    int E = in_sizes[2];

    cudaFuncSetAttribute(k_edge_mma, cudaFuncAttributeMaxDynamicSharedMemorySize, SMEM_BYTES);

    dim3 bgrid(KNOTS / 16, 28);
    k_build<<<bgrid, 256>>>(Wfc1, Wfc2, len, E);                 // #1 (B + hist + scan)
    k_scatterzero<<<(E + 255) / 256, 256>>>(len, E, N * NASTRIDE);  // #2 (scatter + zero)
    k_edge_mma<<<EDGE_GRID, 256, SMEM_BYTES>>>(x, attr, len, src, dst);  // #3 (persistent)
    k_node<<<(N + 15) / 16, 512>>>(x, Wss, Wsv, out, N);         // #4
}